// round 1
// baseline (speedup 1.0000x reference)
#include <cuda_runtime.h>

// ============================================================================
// Fused QKV projection + GQA causal attention, fp32 SIMT baseline.
// B=1, S=2048, H=1024, NH=16, NKV=4, HD=64.  scale = 1/sqrt(1024) = 1/32.
// ============================================================================

#define SEQ 2048
#define HID 1024
#define KVD 256     // NKV * HD
#define SCALE 0.03125f

// Scratch (allocation-free rule: device globals)
__device__ __align__(16) float g_Q[SEQ * HID];
__device__ __align__(16) float g_K[SEQ * KVD];
__device__ __align__(16) float g_V[SEQ * KVD];

// ----------------------------------------------------------------------------
// QKV GEMM: C[M, Ncat] = x[M,1024] @ Wcat[Ncat,1024]^T, Ncat = 1024|256|256.
// BM=BN=128, BK=8, 256 threads, 8x8 micro-tile (split 4+4 rows/cols).
// ----------------------------------------------------------------------------
__global__ __launch_bounds__(256)
void qkv_gemm(const float* __restrict__ x, const float* __restrict__ Wq,
              const float* __restrict__ Wk, const float* __restrict__ Wv)
{
    __shared__ __align__(16) float As[8][128];
    __shared__ __align__(16) float Bs[8][128];

    const int tid = threadIdx.x;
    const int n0 = blockIdx.x * 128;    // combined-N tile start (0..1535)
    const int m0 = blockIdx.y * 128;

    const float* Wbase;
    float* C; int ldc, cbase;
    if (n0 < 1024)      { Wbase = Wq + (size_t)n0 * 1024;          C = g_Q; ldc = 1024; cbase = n0; }
    else if (n0 < 1280) { Wbase = Wk + (size_t)(n0 - 1024) * 1024; C = g_K; ldc = 256;  cbase = n0 - 1024; }
    else                { Wbase = Wv + (size_t)(n0 - 1280) * 1024; C = g_V; ldc = 256;  cbase = n0 - 1280; }

    const int lr = tid >> 1;            // 0..127 tile row for loads
    const int lc = (tid & 1) * 4;       // 0 or 4 (k offset for float4)
    const int tx = tid & 15, ty = tid >> 4;
    const int rA = ty * 4, rB = 64 + ty * 4;
    const int cA = tx * 4, cB = 64 + tx * 4;

    float acc[8][8];
    #pragma unroll
    for (int i = 0; i < 8; i++)
        #pragma unroll
        for (int j = 0; j < 8; j++) acc[i][j] = 0.f;

    const float* xptr = x + (size_t)(m0 + lr) * 1024 + lc;
    const float* wptr = Wbase + (size_t)lr * 1024 + lc;

    for (int k0 = 0; k0 < 1024; k0 += 8) {
        float4 av = *(const float4*)(xptr + k0);
        float4 bv = *(const float4*)(wptr + k0);
        __syncthreads();   // guard previous compute's smem reads
        As[lc + 0][lr] = av.x; As[lc + 1][lr] = av.y; As[lc + 2][lr] = av.z; As[lc + 3][lr] = av.w;
        Bs[lc + 0][lr] = bv.x; Bs[lc + 1][lr] = bv.y; Bs[lc + 2][lr] = bv.z; Bs[lc + 3][lr] = bv.w;
        __syncthreads();
        #pragma unroll
        for (int k = 0; k < 8; k++) {
            float4 a0 = *(const float4*)&As[k][rA];
            float4 a1 = *(const float4*)&As[k][rB];
            float4 b0 = *(const float4*)&Bs[k][cA];
            float4 b1 = *(const float4*)&Bs[k][cB];
            float a[8] = {a0.x, a0.y, a0.z, a0.w, a1.x, a1.y, a1.z, a1.w};
            float b[8] = {b0.x, b0.y, b0.z, b0.w, b1.x, b1.y, b1.z, b1.w};
            #pragma unroll
            for (int i = 0; i < 8; i++)
                #pragma unroll
                for (int j = 0; j < 8; j++)
                    acc[i][j] += a[i] * b[j];
        }
    }

    #pragma unroll
    for (int i = 0; i < 8; i++) {
        int row = (i < 4) ? (rA + i) : (rB + i - 4);
        float* cr = C + (size_t)(m0 + row) * ldc + cbase;
        float4 v0 = make_float4(acc[i][0], acc[i][1], acc[i][2], acc[i][3]);
        float4 v1 = make_float4(acc[i][4], acc[i][5], acc[i][6], acc[i][7]);
        *(float4*)(cr + cA) = v0;
        *(float4*)(cr + cB) = v1;
    }
}

// ----------------------------------------------------------------------------
// Flash attention per (head, 64-row q-tile).  Bc=64.  Online softmax.
// smem: sQ [d][row] (pre-scaled), sKV (K as [d][key], reused as V [key][d]),
//       sS [key][row], plus per-row m/l/alpha and reduction scratch.
// ----------------------------------------------------------------------------
#define ATTN_SMEM_FLOATS (4096 * 3 + 64 * 3 + 256)

__global__ __launch_bounds__(256)
void attn_kernel(float* __restrict__ out)
{
    extern __shared__ float smem[];
    float* sQ     = smem;            // 4096: [d][row]
    float* sKV    = smem + 4096;     // 4096: K transposed, then V natural
    float* sS     = smem + 8192;     // 4096: [key][row]
    float* sMax   = smem + 12288;    // 64
    float* sSum   = smem + 12352;    // 64
    float* sAlpha = smem + 12416;    // 64
    float* sRed   = smem + 12480;    // 4*64

    const int tid = threadIdx.x;
    const int h   = blockIdx.y;
    const int qt  = gridDim.x - 1 - blockIdx.x;   // longest blocks launch first
    const int q0  = qt * 64;
    const int kvh = h >> 2;                        // GQA: head -> kv head

    const int tx = tid & 15, ty = tid >> 4;
    const int ry = ty * 4, cx = tx * 4;            // 4x4 micro-tile coords
    const int row = tid & 63, part = tid >> 6;     // softmax mapping
    const int ldr = tid >> 2;                      // 0..63 row/key for loads
    const int ldd = (tid & 3) * 16;                // d segment for loads

    // Load Q tile, scaled, transposed into [d][row]
    {
        const float* src = g_Q + (size_t)(q0 + ldr) * 1024 + h * 64 + ldd;
        #pragma unroll
        for (int g = 0; g < 4; g++) {
            float4 v = *(const float4*)(src + 4 * g);
            int d = ldd + 4 * g;
            sQ[(d + 0) * 64 + ldr] = v.x * SCALE;
            sQ[(d + 1) * 64 + ldr] = v.y * SCALE;
            sQ[(d + 2) * 64 + ldr] = v.z * SCALE;
            sQ[(d + 3) * 64 + ldr] = v.w * SCALE;
        }
    }
    if (tid < 64) { sMax[tid] = -1e30f; sSum[tid] = 0.f; }

    float o[4][4];
    #pragma unroll
    for (int i = 0; i < 4; i++)
        #pragma unroll
        for (int j = 0; j < 4; j++) o[i][j] = 0.f;

    for (int kt = 0; kt <= qt; kt++) {
        const int k0 = kt * 64;
        __syncthreads();  // A: prior phase2 done with sS/sKV; also covers Q store/init on iter 0

        // Load K tile transposed into [d][key]
        {
            const float* src = g_K + (size_t)(k0 + ldr) * 256 + kvh * 64 + ldd;
            #pragma unroll
            for (int g = 0; g < 4; g++) {
                float4 v = *(const float4*)(src + 4 * g);
                int d = ldd + 4 * g;
                sKV[(d + 0) * 64 + ldr] = v.x;
                sKV[(d + 1) * 64 + ldr] = v.y;
                sKV[(d + 2) * 64 + ldr] = v.z;
                sKV[(d + 3) * 64 + ldr] = v.w;
            }
        }
        __syncthreads();  // B

        // Phase 1: S = Q @ K^T (64x64x64, outer product over d)
        float s[4][4];
        #pragma unroll
        for (int i = 0; i < 4; i++)
            #pragma unroll
            for (int j = 0; j < 4; j++) s[i][j] = 0.f;
        #pragma unroll 8
        for (int d = 0; d < 64; d++) {
            float4 q4 = *(const float4*)&sQ[d * 64 + ry];
            float4 k4 = *(const float4*)&sKV[d * 64 + cx];
            float qa[4] = {q4.x, q4.y, q4.z, q4.w};
            float ka[4] = {k4.x, k4.y, k4.z, k4.w};
            #pragma unroll
            for (int i = 0; i < 4; i++)
                #pragma unroll
                for (int j = 0; j < 4; j++)
                    s[i][j] += qa[i] * ka[j];
        }
        #pragma unroll
        for (int j = 0; j < 4; j++)
            *(float4*)&sS[(cx + j) * 64 + ry] = make_float4(s[0][j], s[1][j], s[2][j], s[3][j]);
        __syncthreads();  // C

        // Softmax: row max (causal-masked)
        float mloc = -1e30f;
        #pragma unroll
        for (int jj = 0; jj < 16; jj++) {
            int j = part * 16 + jj;
            float sv = sS[j * 64 + row];
            mloc = fmaxf(mloc, (k0 + j <= q0 + row) ? sv : -1e30f);
        }
        sRed[part * 64 + row] = mloc;
        __syncthreads();  // D
        if (tid < 64) {
            float mnew = fmaxf(fmaxf(sRed[row], sRed[64 + row]),
                               fmaxf(sRed[128 + row], sRed[192 + row]));
            float mold = sMax[row];
            float mtot = fmaxf(mold, mnew);
            sAlpha[row] = __expf(mold - mtot);
            sMax[row] = mtot;
        }
        __syncthreads();  // E

        // Softmax: exponentiate in place, partial row sums
        {
            float mrow = sMax[row];
            float ssum = 0.f;
            #pragma unroll
            for (int jj = 0; jj < 16; jj++) {
                int j = part * 16 + jj;
                int idx = j * 64 + row;
                float p = (k0 + j <= q0 + row) ? __expf(sS[idx] - mrow) : 0.f;
                sS[idx] = p;
                ssum += p;
            }
            sRed[part * 64 + row] = ssum;
        }

        // Load V tile (natural [key][d]) over the K buffer — K reads ended at C
        {
            const float* src = g_V + (size_t)(k0 + ldr) * 256 + kvh * 64 + ldd;
            float* dst = &sKV[ldr * 64 + ldd];
            *(float4*)(dst + 0)  = *(const float4*)(src + 0);
            *(float4*)(dst + 4)  = *(const float4*)(src + 4);
            *(float4*)(dst + 8)  = *(const float4*)(src + 8);
            *(float4*)(dst + 12) = *(const float4*)(src + 12);
        }
        __syncthreads();  // F

        if (tid < 64) {
            float lsum = sRed[row] + sRed[64 + row] + sRed[128 + row] + sRed[192 + row];
            sSum[row] = sSum[row] * sAlpha[row] + lsum;
        }

        // Phase 2: O = O*alpha + P @ V
        float al[4] = {sAlpha[ry], sAlpha[ry + 1], sAlpha[ry + 2], sAlpha[ry + 3]};
        #pragma unroll
        for (int i = 0; i < 4; i++)
            #pragma unroll
            for (int j = 0; j < 4; j++) o[i][j] *= al[i];
        #pragma unroll 4
        for (int j = 0; j < 64; j++) {
            float4 p4 = *(const float4*)&sS[j * 64 + ry];
            float4 v4 = *(const float4*)&sKV[j * 64 + cx];
            float pa[4] = {p4.x, p4.y, p4.z, p4.w};
            float va[4] = {v4.x, v4.y, v4.z, v4.w};
            #pragma unroll
            for (int i = 0; i < 4; i++)
                #pragma unroll
                for (int jj = 0; jj < 4; jj++)
                    o[i][jj] += pa[i] * va[jj];
        }
    }

    __syncthreads();
    #pragma unroll
    for (int i = 0; i < 4; i++) {
        float inv = 1.0f / sSum[ry + i];
        float4 r = make_float4(o[i][0] * inv, o[i][1] * inv, o[i][2] * inv, o[i][3] * inv);
        *(float4*)&out[(size_t)(q0 + ry + i) * 1024 + h * 64 + cx] = r;
    }
}

// ----------------------------------------------------------------------------
extern "C" void kernel_launch(void* const* d_in, const int* in_sizes, int n_in,
                              void* d_out, int out_size)
{
    const float* x  = (const float*)d_in[0];
    const float* Wq = (const float*)d_in[1];
    const float* Wk = (const float*)d_in[2];
    const float* Wv = (const float*)d_in[3];
    float* out = (float*)d_out;

    cudaFuncSetAttribute(attn_kernel, cudaFuncAttributeMaxDynamicSharedMemorySize,
                         ATTN_SMEM_FLOATS * 4);

    qkv_gemm<<<dim3(12, 16), 256>>>(x, Wq, Wk, Wv);
    attn_kernel<<<dim3(32, 16), 256, ATTN_SMEM_FLOATS * 4>>>(out);
}

// round 2
// speedup vs baseline: 2.4574x; 2.4574x over previous
#include <cuda_runtime.h>
#include <cuda_bf16.h>
#include <cstdint>

// ============================================================================
// Fused QKV projection + GQA causal attention via split-bf16 3-pass mma.sync.
// B=1, S=2048, H=1024, NH=16, NKV=4, HD=64. scale = 1/sqrt(1024) = 1/32.
// fp32 emulation: x = xh + xl (bf16); x*y ~= xh*yh + xh*yl + xl*yh.
// ============================================================================

#define SEQ 2048
#define HID 1024
#define KVD 256
#define SCALE 0.03125f

// Scratch planes (allocation-free rule: device globals)
__device__ __align__(16) __nv_bfloat16 g_xh[SEQ*HID],  g_xl[SEQ*HID];
__device__ __align__(16) __nv_bfloat16 g_wh[1536*HID], g_wl[1536*HID];
__device__ __align__(16) __nv_bfloat16 g_Qh[SEQ*HID],  g_Ql[SEQ*HID];
__device__ __align__(16) __nv_bfloat16 g_Kh[SEQ*KVD],  g_Kl[SEQ*KVD];
__device__ __align__(16) __nv_bfloat16 g_Vth[KVD*SEQ], g_Vtl[KVD*SEQ];  // V transposed [d][seq]

__device__ __forceinline__ void split2(float v, __nv_bfloat16* h, __nv_bfloat16* l) {
    __nv_bfloat16 hh = __float2bfloat16(v);
    *h = hh;
    *l = __float2bfloat16(v - __bfloat162float(hh));
}

#define MMA_BF16(c, a0,a1,a2,a3, b0,b1) \
    asm volatile("mma.sync.aligned.m16n8k16.row.col.f32.bf16.bf16.f32 " \
        "{%0,%1,%2,%3}, {%4,%5,%6,%7}, {%8,%9}, {%0,%1,%2,%3};" \
        : "+f"((c)[0]), "+f"((c)[1]), "+f"((c)[2]), "+f"((c)[3]) \
        : "r"(a0), "r"(a1), "r"(a2), "r"(a3), "r"(b0), "r"(b1))

// ----------------------------------------------------------------------------
// Prep: split x and concatenated W into bf16 hi/lo planes.
// ----------------------------------------------------------------------------
__global__ void split_prep(const float* __restrict__ x, const float* __restrict__ Wq,
                           const float* __restrict__ Wk, const float* __restrict__ Wv)
{
    const int stride = gridDim.x * blockDim.x;
    const int t0 = blockIdx.x * blockDim.x + threadIdx.x;
    for (int i = t0; i < SEQ*HID; i += stride)
        split2(x[i], &g_xh[i], &g_xl[i]);
    for (int i = t0; i < 1536*HID; i += stride) {
        int r = i >> 10;
        float v;
        if (r < 1024)      v = Wq[i];
        else if (r < 1280) v = Wk[i - 1024*1024];
        else               v = Wv[i - 1280*1024];
        split2(v, &g_wh[i], &g_wl[i]);
    }
}

// ----------------------------------------------------------------------------
// QKV GEMM: [2048 x 1536] = x @ Wcat^T. BM=128, BN=64, BK=32, 8 warps (4x2),
// warp tile 32x32, 3-pass split-bf16 mma. Epilogue writes split planes
// (Q scaled; V transposed).
// ----------------------------------------------------------------------------
__global__ __launch_bounds__(256)
void qkv_mma()
{
    __shared__ uint32_t sAh[128*20], sAl[128*20], sBh[64*20], sBl[64*20];
    const int tid = threadIdx.x, lane = tid & 31, warp = tid >> 5;
    const int m0 = blockIdx.y * 128, n0 = blockIdx.x * 64;
    const int wm = warp >> 1, wn = warp & 1;

    float c[2][4][4];
    #pragma unroll
    for (int a = 0; a < 2; a++)
        #pragma unroll
        for (int b = 0; b < 4; b++)
            #pragma unroll
            for (int d = 0; d < 4; d++) c[a][b][d] = 0.f;

    const int ar = tid >> 1, ac = (tid & 1) * 8;   // A: 2 thr/row, 2 uint4 each
    const int br = tid >> 2, bc = (tid & 3) * 4;   // B: 4 thr/row, 1 uint4 each
    const __nv_bfloat16* xh = g_xh + (size_t)(m0 + ar) * HID;
    const __nv_bfloat16* xl = g_xl + (size_t)(m0 + ar) * HID;
    const __nv_bfloat16* wh = g_wh + (size_t)(n0 + br) * HID;
    const __nv_bfloat16* wl = g_wl + (size_t)(n0 + br) * HID;

    for (int k0 = 0; k0 < HID; k0 += 32) {
        uint4 vah0 = *(const uint4*)(xh + k0 + ac*2);
        uint4 vah1 = *(const uint4*)(xh + k0 + ac*2 + 8);
        uint4 val0 = *(const uint4*)(xl + k0 + ac*2);
        uint4 val1 = *(const uint4*)(xl + k0 + ac*2 + 8);
        uint4 vbh  = *(const uint4*)(wh + k0 + bc*2);
        uint4 vbl  = *(const uint4*)(wl + k0 + bc*2);
        __syncthreads();
        *(uint4*)&sAh[ar*20 + ac]     = vah0;
        *(uint4*)&sAh[ar*20 + ac + 4] = vah1;
        *(uint4*)&sAl[ar*20 + ac]     = val0;
        *(uint4*)&sAl[ar*20 + ac + 4] = val1;
        *(uint4*)&sBh[br*20 + bc] = vbh;
        *(uint4*)&sBl[br*20 + bc] = vbl;
        __syncthreads();
        #pragma unroll
        for (int ks = 0; ks < 2; ks++) {
            const int kc = ks*8 + (lane & 3);
            uint32_t Ah[2][4], Al[2][4];
            #pragma unroll
            for (int mt = 0; mt < 2; mt++) {
                int r = wm*32 + mt*16 + (lane >> 2);
                Ah[mt][0] = sAh[r*20 + kc];       Ah[mt][1] = sAh[(r+8)*20 + kc];
                Ah[mt][2] = sAh[r*20 + kc + 4];   Ah[mt][3] = sAh[(r+8)*20 + kc + 4];
                Al[mt][0] = sAl[r*20 + kc];       Al[mt][1] = sAl[(r+8)*20 + kc];
                Al[mt][2] = sAl[r*20 + kc + 4];   Al[mt][3] = sAl[(r+8)*20 + kc + 4];
            }
            #pragma unroll
            for (int nt = 0; nt < 4; nt++) {
                int n = wn*32 + nt*8 + (lane >> 2);
                uint32_t Bh0 = sBh[n*20 + kc], Bh1 = sBh[n*20 + kc + 4];
                uint32_t Bl0 = sBl[n*20 + kc], Bl1 = sBl[n*20 + kc + 4];
                #pragma unroll
                for (int mt = 0; mt < 2; mt++) {
                    MMA_BF16(c[mt][nt], Ah[mt][0],Ah[mt][1],Ah[mt][2],Ah[mt][3], Bh0, Bh1);
                    MMA_BF16(c[mt][nt], Ah[mt][0],Ah[mt][1],Ah[mt][2],Ah[mt][3], Bl0, Bl1);
                    MMA_BF16(c[mt][nt], Al[mt][0],Al[mt][1],Al[mt][2],Al[mt][3], Bh0, Bh1);
                }
            }
        }
    }

    // Epilogue: split-write to destination planes
    #pragma unroll
    for (int mt = 0; mt < 2; mt++) {
        int r0 = m0 + wm*32 + mt*16 + (lane >> 2);
        #pragma unroll
        for (int nt = 0; nt < 4; nt++) {
            int col = n0 + wn*32 + nt*8 + 2*(lane & 3);
            float v0 = c[mt][nt][0], v1 = c[mt][nt][1];
            float v2 = c[mt][nt][2], v3 = c[mt][nt][3];
            if (n0 < 1024) {
                v0 *= SCALE; v1 *= SCALE; v2 *= SCALE; v3 *= SCALE;
                __nv_bfloat16 h0,l0,h1,l1,h2,l2,h3,l3;
                split2(v0,&h0,&l0); split2(v1,&h1,&l1);
                split2(v2,&h2,&l2); split2(v3,&h3,&l3);
                __nv_bfloat162 ph0; ph0.x = h0; ph0.y = h1;
                __nv_bfloat162 pl0; pl0.x = l0; pl0.y = l1;
                __nv_bfloat162 ph1; ph1.x = h2; ph1.y = h3;
                __nv_bfloat162 pl1; pl1.x = l2; pl1.y = l3;
                *(__nv_bfloat162*)&g_Qh[(size_t)r0*HID + col]     = ph0;
                *(__nv_bfloat162*)&g_Ql[(size_t)r0*HID + col]     = pl0;
                *(__nv_bfloat162*)&g_Qh[(size_t)(r0+8)*HID + col] = ph1;
                *(__nv_bfloat162*)&g_Ql[(size_t)(r0+8)*HID + col] = pl1;
            } else if (n0 < 1280) {
                int kc2 = col - 1024;
                __nv_bfloat16 h0,l0,h1,l1,h2,l2,h3,l3;
                split2(v0,&h0,&l0); split2(v1,&h1,&l1);
                split2(v2,&h2,&l2); split2(v3,&h3,&l3);
                __nv_bfloat162 ph0; ph0.x = h0; ph0.y = h1;
                __nv_bfloat162 pl0; pl0.x = l0; pl0.y = l1;
                __nv_bfloat162 ph1; ph1.x = h2; ph1.y = h3;
                __nv_bfloat162 pl1; pl1.x = l2; pl1.y = l3;
                *(__nv_bfloat162*)&g_Kh[(size_t)r0*KVD + kc2]     = ph0;
                *(__nv_bfloat162*)&g_Kl[(size_t)r0*KVD + kc2]     = pl0;
                *(__nv_bfloat162*)&g_Kh[(size_t)(r0+8)*KVD + kc2] = ph1;
                *(__nv_bfloat162*)&g_Kl[(size_t)(r0+8)*KVD + kc2] = pl1;
            } else {
                int vc = col - 1280;   // V transposed scatter: g_Vt[d][seq]
                __nv_bfloat16 h, l;
                split2(v0,&h,&l); g_Vth[(size_t)vc*SEQ + r0]       = h; g_Vtl[(size_t)vc*SEQ + r0]       = l;
                split2(v1,&h,&l); g_Vth[(size_t)(vc+1)*SEQ + r0]   = h; g_Vtl[(size_t)(vc+1)*SEQ + r0]   = l;
                split2(v2,&h,&l); g_Vth[(size_t)vc*SEQ + r0+8]     = h; g_Vtl[(size_t)vc*SEQ + r0+8]     = l;
                split2(v3,&h,&l); g_Vth[(size_t)(vc+1)*SEQ + r0+8] = h; g_Vtl[(size_t)(vc+1)*SEQ + r0+8] = l;
            }
        }
    }
}

// ----------------------------------------------------------------------------
// Attention: per (head, 64-q-tile), Bc=64, online softmax. Both GEMM phases
// via 3-pass split-bf16 mma. 8 warps, warp tile 16x32.
// smem (u32 offsets):
// ----------------------------------------------------------------------------
#define AQH 0          // Q hi  [64][36] u32 (packed bf16 pairs along d)
#define AQL 2304       // Q lo
#define ABH 4608       // K hi [key][dpack] -> later P hi [m][keypack]
#define ABL 6912
#define AVH 9216       // V^T hi [d][keypack]
#define AVL 11520
#define ASS 13824      // S fp32, col-major, stride 65 (4160 floats)
#define AMAX 17984
#define ASUM 18048
#define AALPHA 18112
#define ARED 18176     // 256
#define ATTN_U32 18432

__global__ __launch_bounds__(256)
void attn_mma(float* __restrict__ out)
{
    extern __shared__ uint32_t sm[];
    float* sS     = (float*)(sm + ASS);
    float* sMax   = (float*)(sm + AMAX);
    float* sSum   = (float*)(sm + ASUM);
    float* sAlpha = (float*)(sm + AALPHA);
    float* sRed   = (float*)(sm + ARED);

    const int tid = threadIdx.x, lane = tid & 31, warp = tid >> 5;
    const int h   = blockIdx.y;
    const int qt  = gridDim.x - 1 - blockIdx.x;   // longest first
    const int q0  = qt * 64;
    const int kvh = h >> 2;
    const int wm  = warp >> 1, wn = warp & 1;

    const int ldr = tid >> 2;        // 0..63 row for tile loads
    const int seg = tid & 3;         // u32 col segment (seg*8, seg*8+4)

    // Load Q tile (pre-scaled, pre-split)
    {
        const __nv_bfloat16* qh = g_Qh + (size_t)(q0 + ldr) * HID + h*64 + seg*16;
        const __nv_bfloat16* ql = g_Ql + (size_t)(q0 + ldr) * HID + h*64 + seg*16;
        *(uint4*)&sm[AQH + ldr*36 + seg*8]     = *(const uint4*)qh;
        *(uint4*)&sm[AQH + ldr*36 + seg*8 + 4] = *(const uint4*)(qh + 8);
        *(uint4*)&sm[AQL + ldr*36 + seg*8]     = *(const uint4*)ql;
        *(uint4*)&sm[AQL + ldr*36 + seg*8 + 4] = *(const uint4*)(ql + 8);
    }
    if (tid < 64) { sMax[tid] = -1e30f; sSum[tid] = 0.f; }

    float o[4][4];
    #pragma unroll
    for (int i = 0; i < 4; i++)
        #pragma unroll
        for (int j = 0; j < 4; j++) o[i][j] = 0.f;

    const int srow = tid & 63, part = tid >> 6;
    const int fr = wm*16 + (lane >> 2);           // fragment row (m)
    const int fq = lane & 3;

    for (int kt = 0; kt <= qt; kt++) {
        const int k0 = kt * 64;
        __syncthreads();  // A: prev phase2 done with ABH/ABL/AVH/AVL

        // Load K tile [key][dpack] and V^T tile [d][keypack]
        {
            const __nv_bfloat16* kh = g_Kh + (size_t)(k0 + ldr) * KVD + kvh*64 + seg*16;
            const __nv_bfloat16* kl = g_Kl + (size_t)(k0 + ldr) * KVD + kvh*64 + seg*16;
            *(uint4*)&sm[ABH + ldr*36 + seg*8]     = *(const uint4*)kh;
            *(uint4*)&sm[ABH + ldr*36 + seg*8 + 4] = *(const uint4*)(kh + 8);
            *(uint4*)&sm[ABL + ldr*36 + seg*8]     = *(const uint4*)kl;
            *(uint4*)&sm[ABL + ldr*36 + seg*8 + 4] = *(const uint4*)(kl + 8);
            const __nv_bfloat16* vh = g_Vth + (size_t)(kvh*64 + ldr) * SEQ + k0 + seg*16;
            const __nv_bfloat16* vl = g_Vtl + (size_t)(kvh*64 + ldr) * SEQ + k0 + seg*16;
            *(uint4*)&sm[AVH + ldr*36 + seg*8]     = *(const uint4*)vh;
            *(uint4*)&sm[AVH + ldr*36 + seg*8 + 4] = *(const uint4*)(vh + 8);
            *(uint4*)&sm[AVL + ldr*36 + seg*8]     = *(const uint4*)vl;
            *(uint4*)&sm[AVL + ldr*36 + seg*8 + 4] = *(const uint4*)(vl + 8);
        }
        __syncthreads();  // B

        // ---- Phase 1: S = Q @ K^T ----
        float s4[4][4];
        #pragma unroll
        for (int i = 0; i < 4; i++)
            #pragma unroll
            for (int j = 0; j < 4; j++) s4[i][j] = 0.f;
        #pragma unroll
        for (int ks = 0; ks < 4; ks++) {
            const int kc = ks*8 + fq;
            uint32_t Ah0 = sm[AQH + fr*36 + kc],     Ah1 = sm[AQH + (fr+8)*36 + kc];
            uint32_t Ah2 = sm[AQH + fr*36 + kc + 4], Ah3 = sm[AQH + (fr+8)*36 + kc + 4];
            uint32_t Al0 = sm[AQL + fr*36 + kc],     Al1 = sm[AQL + (fr+8)*36 + kc];
            uint32_t Al2 = sm[AQL + fr*36 + kc + 4], Al3 = sm[AQL + (fr+8)*36 + kc + 4];
            #pragma unroll
            for (int nt = 0; nt < 4; nt++) {
                int n = wn*32 + nt*8 + (lane >> 2);
                uint32_t Bh0 = sm[ABH + n*36 + kc], Bh1 = sm[ABH + n*36 + kc + 4];
                uint32_t Bl0 = sm[ABL + n*36 + kc], Bl1 = sm[ABL + n*36 + kc + 4];
                MMA_BF16(s4[nt], Ah0,Ah1,Ah2,Ah3, Bh0,Bh1);
                MMA_BF16(s4[nt], Ah0,Ah1,Ah2,Ah3, Bl0,Bl1);
                MMA_BF16(s4[nt], Al0,Al1,Al2,Al3, Bh0,Bh1);
            }
        }
        // write S col-major stride 65
        #pragma unroll
        for (int nt = 0; nt < 4; nt++) {
            int col = wn*32 + nt*8 + 2*fq;
            sS[col*65 + fr]         = s4[nt][0];
            sS[(col+1)*65 + fr]     = s4[nt][1];
            sS[col*65 + fr + 8]     = s4[nt][2];
            sS[(col+1)*65 + fr + 8] = s4[nt][3];
        }
        __syncthreads();  // C

        // ---- Softmax: row max ----
        float mloc = -1e30f;
        #pragma unroll
        for (int jj = 0; jj < 16; jj++) {
            int j = part*16 + jj;
            float sv = sS[j*65 + srow];
            mloc = fmaxf(mloc, (k0 + j <= q0 + srow) ? sv : -1e30f);
        }
        sRed[part*64 + srow] = mloc;
        __syncthreads();  // D
        if (tid < 64) {
            float mnew = fmaxf(fmaxf(sRed[tid], sRed[64+tid]),
                               fmaxf(sRed[128+tid], sRed[192+tid]));
            float mold = sMax[tid];
            float mtot = fmaxf(mold, mnew);
            sAlpha[tid] = __expf(mold - mtot);
            sMax[tid] = mtot;
        }
        __syncthreads();  // E

        // ---- exp + split-pack P into ABH/ABL, partial sums ----
        {
            float mrow = sMax[srow];
            float ssum = 0.f;
            #pragma unroll
            for (int jj = 0; jj < 16; jj += 2) {
                int j = part*16 + jj;
                float p0 = (k0 + j     <= q0 + srow) ? __expf(sS[j*65 + srow]     - mrow) : 0.f;
                float p1 = (k0 + j + 1 <= q0 + srow) ? __expf(sS[(j+1)*65 + srow] - mrow) : 0.f;
                ssum += p0 + p1;
                __nv_bfloat16 h0,l0,h1,l1;
                split2(p0,&h0,&l0); split2(p1,&h1,&l1);
                __nv_bfloat162 hp; hp.x = h0; hp.y = h1;
                __nv_bfloat162 lp; lp.x = l0; lp.y = l1;
                sm[ABH + srow*36 + part*8 + (jj >> 1)] = *(uint32_t*)&hp;
                sm[ABL + srow*36 + part*8 + (jj >> 1)] = *(uint32_t*)&lp;
            }
            sRed[part*64 + srow] = ssum;
        }
        __syncthreads();  // F

        if (tid < 64)
            sSum[tid] = sSum[tid]*sAlpha[tid]
                      + sRed[tid] + sRed[64+tid] + sRed[128+tid] + sRed[192+tid];

        // ---- rescale O, Phase 2: O += P @ V ----
        {
            float a0 = sAlpha[fr];
            float a1 = sAlpha[fr + 8];
            #pragma unroll
            for (int nt = 0; nt < 4; nt++) {
                o[nt][0] *= a0; o[nt][1] *= a0;
                o[nt][2] *= a1; o[nt][3] *= a1;
            }
        }
        #pragma unroll
        for (int ks = 0; ks < 4; ks++) {
            const int kc = ks*8 + fq;
            uint32_t Ah0 = sm[ABH + fr*36 + kc],     Ah1 = sm[ABH + (fr+8)*36 + kc];
            uint32_t Ah2 = sm[ABH + fr*36 + kc + 4], Ah3 = sm[ABH + (fr+8)*36 + kc + 4];
            uint32_t Al0 = sm[ABL + fr*36 + kc],     Al1 = sm[ABL + (fr+8)*36 + kc];
            uint32_t Al2 = sm[ABL + fr*36 + kc + 4], Al3 = sm[ABL + (fr+8)*36 + kc + 4];
            #pragma unroll
            for (int nt = 0; nt < 4; nt++) {
                int n = wn*32 + nt*8 + (lane >> 2);
                uint32_t Bh0 = sm[AVH + n*36 + kc], Bh1 = sm[AVH + n*36 + kc + 4];
                uint32_t Bl0 = sm[AVL + n*36 + kc], Bl1 = sm[AVL + n*36 + kc + 4];
                MMA_BF16(o[nt], Ah0,Ah1,Ah2,Ah3, Bh0,Bh1);
                MMA_BF16(o[nt], Ah0,Ah1,Ah2,Ah3, Bl0,Bl1);
                MMA_BF16(o[nt], Al0,Al1,Al2,Al3, Bh0,Bh1);
            }
        }
    }

    __syncthreads();
    {
        float inv0 = 1.f / sSum[fr];
        float inv1 = 1.f / sSum[fr + 8];
        #pragma unroll
        for (int nt = 0; nt < 4; nt++) {
            int col = wn*32 + nt*8 + 2*fq;
            float2 v0 = make_float2(o[nt][0]*inv0, o[nt][1]*inv0);
            float2 v1 = make_float2(o[nt][2]*inv1, o[nt][3]*inv1);
            *(float2*)&out[(size_t)(q0 + fr)*HID + h*64 + col]     = v0;
            *(float2*)&out[(size_t)(q0 + fr + 8)*HID + h*64 + col] = v1;
        }
    }
}

// ----------------------------------------------------------------------------
extern "C" void kernel_launch(void* const* d_in, const int* in_sizes, int n_in,
                              void* d_out, int out_size)
{
    const float* x  = (const float*)d_in[0];
    const float* Wq = (const float*)d_in[1];
    const float* Wk = (const float*)d_in[2];
    const float* Wv = (const float*)d_in[3];
    float* out = (float*)d_out;

    cudaFuncSetAttribute(attn_mma, cudaFuncAttributeMaxDynamicSharedMemorySize,
                         ATTN_U32 * 4);

    split_prep<<<256, 256>>>(x, Wq, Wk, Wv);
    qkv_mma<<<dim3(24, 16), 256>>>();
    attn_mma<<<dim3(32, 16), 256, ATTN_U32 * 4>>>(out);
}

// round 5
// speedup vs baseline: 2.7721x; 1.1281x over previous
#include <cuda_runtime.h>
#include <cuda_bf16.h>
#include <cstdint>

// ============================================================================
// Fused QKV projection + GQA causal attention via split-bf16 3-pass mma.sync.
// Round 4 (= Round 3 resubmit after infra failure): FA2-style register-resident
// attention (warp-owned rows, P in regs, warp-local softmax, 2 syncs/tile,
// Q frags hoisted).
// ============================================================================

#define SEQ 2048
#define HID 1024
#define KVD 256
#define SCALE 0.03125f

__device__ __align__(16) __nv_bfloat16 g_xh[SEQ*HID],  g_xl[SEQ*HID];
__device__ __align__(16) __nv_bfloat16 g_wh[1536*HID], g_wl[1536*HID];
__device__ __align__(16) __nv_bfloat16 g_Qh[SEQ*HID],  g_Ql[SEQ*HID];
__device__ __align__(16) __nv_bfloat16 g_Kh[SEQ*KVD],  g_Kl[SEQ*KVD];
__device__ __align__(16) __nv_bfloat16 g_Vth[KVD*SEQ], g_Vtl[KVD*SEQ];  // V^T [d][seq]

__device__ __forceinline__ void split2(float v, __nv_bfloat16* h, __nv_bfloat16* l) {
    __nv_bfloat16 hh = __float2bfloat16(v);
    *h = hh;
    *l = __float2bfloat16(v - __bfloat162float(hh));
}

#define MMA_BF16(c, a0,a1,a2,a3, b0,b1) \
    asm volatile("mma.sync.aligned.m16n8k16.row.col.f32.bf16.bf16.f32 " \
        "{%0,%1,%2,%3}, {%4,%5,%6,%7}, {%8,%9}, {%0,%1,%2,%3};" \
        : "+f"((c)[0]), "+f"((c)[1]), "+f"((c)[2]), "+f"((c)[3]) \
        : "r"(a0), "r"(a1), "r"(a2), "r"(a3), "r"(b0), "r"(b1))

// ----------------------------------------------------------------------------
// Prep: split x and concatenated W into bf16 hi/lo planes (vectorized).
// ----------------------------------------------------------------------------
__global__ void split_prep(const float* __restrict__ x, const float* __restrict__ Wq,
                           const float* __restrict__ Wk, const float* __restrict__ Wv)
{
    const int stride = gridDim.x * blockDim.x;
    const int t0 = blockIdx.x * blockDim.x + threadIdx.x;

    for (int i4 = t0; i4 < (SEQ*HID)/4; i4 += stride) {
        float4 v = ((const float4*)x)[i4];
        __nv_bfloat16 h0,l0,h1,l1,h2,l2,h3,l3;
        split2(v.x,&h0,&l0); split2(v.y,&h1,&l1);
        split2(v.z,&h2,&l2); split2(v.w,&h3,&l3);
        __nv_bfloat162 hA; hA.x=h0; hA.y=h1;
        __nv_bfloat162 hB; hB.x=h2; hB.y=h3;
        __nv_bfloat162 lA; lA.x=l0; lA.y=l1;
        __nv_bfloat162 lB; lB.x=l2; lB.y=l3;
        ((uint2*)g_xh)[i4] = make_uint2(*(uint32_t*)&hA, *(uint32_t*)&hB);
        ((uint2*)g_xl)[i4] = make_uint2(*(uint32_t*)&lA, *(uint32_t*)&lB);
    }
    for (int i4 = t0; i4 < (1536*HID)/4; i4 += stride) {
        int i = i4 * 4;
        int r = i >> 10;
        float4 v;
        if (r < 1024)      v = *(const float4*)(Wq + i);
        else if (r < 1280) v = *(const float4*)(Wk + i - 1024*1024);
        else               v = *(const float4*)(Wv + i - 1280*1024);
        __nv_bfloat16 h0,l0,h1,l1,h2,l2,h3,l3;
        split2(v.x,&h0,&l0); split2(v.y,&h1,&l1);
        split2(v.z,&h2,&l2); split2(v.w,&h3,&l3);
        __nv_bfloat162 hA; hA.x=h0; hA.y=h1;
        __nv_bfloat162 hB; hB.x=h2; hB.y=h3;
        __nv_bfloat162 lA; lA.x=l0; lA.y=l1;
        __nv_bfloat162 lB; lB.x=l2; lB.y=l3;
        ((uint2*)g_wh)[i4] = make_uint2(*(uint32_t*)&hA, *(uint32_t*)&hB);
        ((uint2*)g_wl)[i4] = make_uint2(*(uint32_t*)&lA, *(uint32_t*)&lB);
    }
}

// ----------------------------------------------------------------------------
// QKV GEMM: [2048 x 1536] = x @ Wcat^T.  (unchanged from round 2, known-good)
// ----------------------------------------------------------------------------
__global__ __launch_bounds__(256)
void qkv_mma()
{
    __shared__ uint32_t sAh[128*20], sAl[128*20], sBh[64*20], sBl[64*20];
    const int tid = threadIdx.x, lane = tid & 31, warp = tid >> 5;
    const int m0 = blockIdx.y * 128, n0 = blockIdx.x * 64;
    const int wm = warp >> 1, wn = warp & 1;

    float c[2][4][4];
    #pragma unroll
    for (int a = 0; a < 2; a++)
        #pragma unroll
        for (int b = 0; b < 4; b++)
            #pragma unroll
            for (int d = 0; d < 4; d++) c[a][b][d] = 0.f;

    const int ar = tid >> 1, ac = (tid & 1) * 8;
    const int br = tid >> 2, bc = (tid & 3) * 4;
    const __nv_bfloat16* xh = g_xh + (size_t)(m0 + ar) * HID;
    const __nv_bfloat16* xl = g_xl + (size_t)(m0 + ar) * HID;
    const __nv_bfloat16* wh = g_wh + (size_t)(n0 + br) * HID;
    const __nv_bfloat16* wl = g_wl + (size_t)(n0 + br) * HID;

    for (int k0 = 0; k0 < HID; k0 += 32) {
        uint4 vah0 = *(const uint4*)(xh + k0 + ac*2);
        uint4 vah1 = *(const uint4*)(xh + k0 + ac*2 + 8);
        uint4 val0 = *(const uint4*)(xl + k0 + ac*2);
        uint4 val1 = *(const uint4*)(xl + k0 + ac*2 + 8);
        uint4 vbh  = *(const uint4*)(wh + k0 + bc*2);
        uint4 vbl  = *(const uint4*)(wl + k0 + bc*2);
        __syncthreads();
        *(uint4*)&sAh[ar*20 + ac]     = vah0;
        *(uint4*)&sAh[ar*20 + ac + 4] = vah1;
        *(uint4*)&sAl[ar*20 + ac]     = val0;
        *(uint4*)&sAl[ar*20 + ac + 4] = val1;
        *(uint4*)&sBh[br*20 + bc] = vbh;
        *(uint4*)&sBl[br*20 + bc] = vbl;
        __syncthreads();
        #pragma unroll
        for (int ks = 0; ks < 2; ks++) {
            const int kc = ks*8 + (lane & 3);
            uint32_t Ah[2][4], Al[2][4];
            #pragma unroll
            for (int mt = 0; mt < 2; mt++) {
                int r = wm*32 + mt*16 + (lane >> 2);
                Ah[mt][0] = sAh[r*20 + kc];       Ah[mt][1] = sAh[(r+8)*20 + kc];
                Ah[mt][2] = sAh[r*20 + kc + 4];   Ah[mt][3] = sAh[(r+8)*20 + kc + 4];
                Al[mt][0] = sAl[r*20 + kc];       Al[mt][1] = sAl[(r+8)*20 + kc];
                Al[mt][2] = sAl[r*20 + kc + 4];   Al[mt][3] = sAl[(r+8)*20 + kc + 4];
            }
            #pragma unroll
            for (int nt = 0; nt < 4; nt++) {
                int n = wn*32 + nt*8 + (lane >> 2);
                uint32_t Bh0 = sBh[n*20 + kc], Bh1 = sBh[n*20 + kc + 4];
                uint32_t Bl0 = sBl[n*20 + kc], Bl1 = sBl[n*20 + kc + 4];
                #pragma unroll
                for (int mt = 0; mt < 2; mt++) {
                    MMA_BF16(c[mt][nt], Ah[mt][0],Ah[mt][1],Ah[mt][2],Ah[mt][3], Bh0, Bh1);
                    MMA_BF16(c[mt][nt], Ah[mt][0],Ah[mt][1],Ah[mt][2],Ah[mt][3], Bl0, Bl1);
                    MMA_BF16(c[mt][nt], Al[mt][0],Al[mt][1],Al[mt][2],Al[mt][3], Bh0, Bh1);
                }
            }
        }
    }

    #pragma unroll
    for (int mt = 0; mt < 2; mt++) {
        int r0 = m0 + wm*32 + mt*16 + (lane >> 2);
        #pragma unroll
        for (int nt = 0; nt < 4; nt++) {
            int col = n0 + wn*32 + nt*8 + 2*(lane & 3);
            float v0 = c[mt][nt][0], v1 = c[mt][nt][1];
            float v2 = c[mt][nt][2], v3 = c[mt][nt][3];
            if (n0 < 1024) {
                v0 *= SCALE; v1 *= SCALE; v2 *= SCALE; v3 *= SCALE;
                __nv_bfloat16 h0,l0,h1,l1,h2,l2,h3,l3;
                split2(v0,&h0,&l0); split2(v1,&h1,&l1);
                split2(v2,&h2,&l2); split2(v3,&h3,&l3);
                __nv_bfloat162 ph0; ph0.x = h0; ph0.y = h1;
                __nv_bfloat162 pl0; pl0.x = l0; pl0.y = l1;
                __nv_bfloat162 ph1; ph1.x = h2; ph1.y = h3;
                __nv_bfloat162 pl1; pl1.x = l2; pl1.y = l3;
                *(__nv_bfloat162*)&g_Qh[(size_t)r0*HID + col]     = ph0;
                *(__nv_bfloat162*)&g_Ql[(size_t)r0*HID + col]     = pl0;
                *(__nv_bfloat162*)&g_Qh[(size_t)(r0+8)*HID + col] = ph1;
                *(__nv_bfloat162*)&g_Ql[(size_t)(r0+8)*HID + col] = pl1;
            } else if (n0 < 1280) {
                int kc2 = col - 1024;
                __nv_bfloat16 h0,l0,h1,l1,h2,l2,h3,l3;
                split2(v0,&h0,&l0); split2(v1,&h1,&l1);
                split2(v2,&h2,&l2); split2(v3,&h3,&l3);
                __nv_bfloat162 ph0; ph0.x = h0; ph0.y = h1;
                __nv_bfloat162 pl0; pl0.x = l0; pl0.y = l1;
                __nv_bfloat162 ph1; ph1.x = h2; ph1.y = h3;
                __nv_bfloat162 pl1; pl1.x = l2; pl1.y = l3;
                *(__nv_bfloat162*)&g_Kh[(size_t)r0*KVD + kc2]     = ph0;
                *(__nv_bfloat162*)&g_Kl[(size_t)r0*KVD + kc2]     = pl0;
                *(__nv_bfloat162*)&g_Kh[(size_t)(r0+8)*KVD + kc2] = ph1;
                *(__nv_bfloat162*)&g_Kl[(size_t)(r0+8)*KVD + kc2] = pl1;
            } else {
                int vc = col - 1280;
                __nv_bfloat16 h, l;
                split2(v0,&h,&l); g_Vth[(size_t)vc*SEQ + r0]       = h; g_Vtl[(size_t)vc*SEQ + r0]       = l;
                split2(v1,&h,&l); g_Vth[(size_t)(vc+1)*SEQ + r0]   = h; g_Vtl[(size_t)(vc+1)*SEQ + r0]   = l;
                split2(v2,&h,&l); g_Vth[(size_t)vc*SEQ + r0+8]     = h; g_Vtl[(size_t)vc*SEQ + r0+8]     = l;
                split2(v3,&h,&l); g_Vth[(size_t)(vc+1)*SEQ + r0+8] = h; g_Vtl[(size_t)(vc+1)*SEQ + r0+8] = l;
            }
        }
    }
}

// ----------------------------------------------------------------------------
// Attention: Br=128 rows/block (8 warps x 16 rows, full 64-key width per warp),
// Bc=64. P + softmax state entirely in registers. 2 syncs per kv-tile.
// smem u32 layout: KH[64*36] KL[64*36] VH[64*36] VL[64*36]  (36KB)
// ----------------------------------------------------------------------------
#define KH 0
#define KL 2304
#define VH 4608
#define VL 6912

__global__ __launch_bounds__(256)
void attn_mma(float* __restrict__ out)
{
    __shared__ uint32_t sm[9216];

    const int tid = threadIdx.x, lane = tid & 31, w = tid >> 5;
    const int h  = blockIdx.y;
    const int qt = gridDim.x - 1 - blockIdx.x;     // longest first
    const int q0 = qt * 128;
    const int kvh = h >> 2;
    const int fq = lane & 3, fr8 = lane >> 2;
    const int warp_row = q0 + w*16 + fr8;          // global row of fragment row r0

    // ---- Stage Q (hi into [0..4607], lo into [4608..9215]), read frags ----
    {
        const int row = tid >> 1, half = (tid & 1) * 16;   // 16 u32 = 32 bf16
        const __nv_bfloat16* qh = g_Qh + (size_t)(q0 + row) * HID + h*64 + half*2;
        const __nv_bfloat16* ql = g_Ql + (size_t)(q0 + row) * HID + h*64 + half*2;
        #pragma unroll
        for (int g = 0; g < 4; g++) {
            *(uint4*)&sm[row*36 + half + g*4]        = *(const uint4*)(qh + g*8);
            *(uint4*)&sm[4608 + row*36 + half + g*4] = *(const uint4*)(ql + g*8);
        }
    }
    __syncthreads();

    uint32_t qfh[4][4], qfl[4][4];
    {
        const int r0 = w*16 + fr8;
        #pragma unroll
        for (int ks = 0; ks < 4; ks++) {
            int kc = ks*8 + fq;
            qfh[ks][0] = sm[r0*36 + kc];            qfh[ks][1] = sm[(r0+8)*36 + kc];
            qfh[ks][2] = sm[r0*36 + kc + 4];        qfh[ks][3] = sm[(r0+8)*36 + kc + 4];
            qfl[ks][0] = sm[4608 + r0*36 + kc];     qfl[ks][1] = sm[4608 + (r0+8)*36 + kc];
            qfl[ks][2] = sm[4608 + r0*36 + kc + 4]; qfl[ks][3] = sm[4608 + (r0+8)*36 + kc + 4];
        }
    }

    float o[8][4];
    #pragma unroll
    for (int nt = 0; nt < 8; nt++)
        #pragma unroll
        for (int j = 0; j < 4; j++) o[nt][j] = 0.f;
    float m0 = -1e30f, m1 = -1e30f, l0 = 0.f, l1 = 0.f;

    const int ldr = tid >> 2, seg = tid & 3;
    const int ktmax = 2*qt + 1;

    for (int kt = 0; kt <= ktmax; kt++) {
        const int k0 = kt * 64;
        __syncthreads();  // previous tile's smem reads done

        // Load K [key][dpack] and V^T [d][keypack] hi/lo
        {
            const __nv_bfloat16* kh = g_Kh + (size_t)(k0 + ldr) * KVD + kvh*64 + seg*16;
            const __nv_bfloat16* kl = g_Kl + (size_t)(k0 + ldr) * KVD + kvh*64 + seg*16;
            *(uint4*)&sm[KH + ldr*36 + seg*8]     = *(const uint4*)kh;
            *(uint4*)&sm[KH + ldr*36 + seg*8 + 4] = *(const uint4*)(kh + 8);
            *(uint4*)&sm[KL + ldr*36 + seg*8]     = *(const uint4*)kl;
            *(uint4*)&sm[KL + ldr*36 + seg*8 + 4] = *(const uint4*)(kl + 8);
            const __nv_bfloat16* vh = g_Vth + (size_t)(kvh*64 + ldr) * SEQ + k0 + seg*16;
            const __nv_bfloat16* vl = g_Vtl + (size_t)(kvh*64 + ldr) * SEQ + k0 + seg*16;
            *(uint4*)&sm[VH + ldr*36 + seg*8]     = *(const uint4*)vh;
            *(uint4*)&sm[VH + ldr*36 + seg*8 + 4] = *(const uint4*)(vh + 8);
            *(uint4*)&sm[VL + ldr*36 + seg*8]     = *(const uint4*)vl;
            *(uint4*)&sm[VL + ldr*36 + seg*8 + 4] = *(const uint4*)(vl + 8);
        }
        __syncthreads();

        // Warps entirely above the causal boundary skip this tile
        if (k0 > q0 + w*16 + 15) continue;

        // ---- Phase 1: S = Q @ K^T ----
        float s4[8][4];
        #pragma unroll
        for (int nt = 0; nt < 8; nt++)
            #pragma unroll
            for (int j = 0; j < 4; j++) s4[nt][j] = 0.f;
        #pragma unroll
        for (int ks = 0; ks < 4; ks++) {
            const int kc = ks*8 + fq;
            #pragma unroll
            for (int nt = 0; nt < 8; nt++) {
                int n = nt*8 + fr8;
                uint32_t Bh0 = sm[KH + n*36 + kc], Bh1 = sm[KH + n*36 + kc + 4];
                uint32_t Bl0 = sm[KL + n*36 + kc], Bl1 = sm[KL + n*36 + kc + 4];
                MMA_BF16(s4[nt], qfh[ks][0],qfh[ks][1],qfh[ks][2],qfh[ks][3], Bh0,Bh1);
                MMA_BF16(s4[nt], qfh[ks][0],qfh[ks][1],qfh[ks][2],qfh[ks][3], Bl0,Bl1);
                MMA_BF16(s4[nt], qfl[ks][0],qfl[ks][1],qfl[ks][2],qfl[ks][3], Bh0,Bh1);
            }
        }

        // Causal mask (only near the diagonal)
        if (k0 + 63 > warp_row) {
            #pragma unroll
            for (int nt = 0; nt < 8; nt++) {
                int c0 = k0 + nt*8 + 2*fq;
                if (c0     > warp_row    ) s4[nt][0] = -1e30f;
                if (c0 + 1 > warp_row    ) s4[nt][1] = -1e30f;
                if (c0     > warp_row + 8) s4[nt][2] = -1e30f;
                if (c0 + 1 > warp_row + 8) s4[nt][3] = -1e30f;
            }
        }

        // ---- Warp-local online softmax ----
        float t0 = -1e30f, t1 = -1e30f;
        #pragma unroll
        for (int nt = 0; nt < 8; nt++) {
            t0 = fmaxf(t0, fmaxf(s4[nt][0], s4[nt][1]));
            t1 = fmaxf(t1, fmaxf(s4[nt][2], s4[nt][3]));
        }
        t0 = fmaxf(t0, __shfl_xor_sync(0xffffffffu, t0, 1));
        t0 = fmaxf(t0, __shfl_xor_sync(0xffffffffu, t0, 2));
        t1 = fmaxf(t1, __shfl_xor_sync(0xffffffffu, t1, 1));
        t1 = fmaxf(t1, __shfl_xor_sync(0xffffffffu, t1, 2));
        float mn0 = fmaxf(m0, t0), mn1 = fmaxf(m1, t1);
        float a0 = __expf(m0 - mn0), a1 = __expf(m1 - mn1);
        m0 = mn0; m1 = mn1;

        // exp + split-pack P into A-fragments (registers only)
        uint32_t pa_h[8], pa_l[8], pb_h[8], pb_l[8];
        float ls0 = 0.f, ls1 = 0.f;
        #pragma unroll
        for (int nt = 0; nt < 8; nt++) {
            float p0 = __expf(s4[nt][0] - mn0);
            float p1 = __expf(s4[nt][1] - mn0);
            float p2 = __expf(s4[nt][2] - mn1);
            float p3 = __expf(s4[nt][3] - mn1);
            ls0 += p0 + p1; ls1 += p2 + p3;
            __nv_bfloat16 h0,lo0,h1,lo1;
            split2(p0,&h0,&lo0); split2(p1,&h1,&lo1);
            __nv_bfloat162 hp; hp.x=h0; hp.y=h1;
            __nv_bfloat162 lp; lp.x=lo0; lp.y=lo1;
            pa_h[nt] = *(uint32_t*)&hp; pa_l[nt] = *(uint32_t*)&lp;
            split2(p2,&h0,&lo0); split2(p3,&h1,&lo1);
            hp.x=h0; hp.y=h1; lp.x=lo0; lp.y=lo1;
            pb_h[nt] = *(uint32_t*)&hp; pb_l[nt] = *(uint32_t*)&lp;
        }
        ls0 += __shfl_xor_sync(0xffffffffu, ls0, 1);
        ls0 += __shfl_xor_sync(0xffffffffu, ls0, 2);
        ls1 += __shfl_xor_sync(0xffffffffu, ls1, 1);
        ls1 += __shfl_xor_sync(0xffffffffu, ls1, 2);
        l0 = l0*a0 + ls0; l1 = l1*a1 + ls1;

        // rescale O
        #pragma unroll
        for (int nt = 0; nt < 8; nt++) {
            o[nt][0] *= a0; o[nt][1] *= a0;
            o[nt][2] *= a1; o[nt][3] *= a1;
        }

        // ---- Phase 2: O += P @ V (A = P regs, B = V^T smem) ----
        #pragma unroll
        for (int ks = 0; ks < 4; ks++) {
            const int kc = ks*8 + fq;
            uint32_t Ah0 = pa_h[2*ks], Ah1 = pb_h[2*ks], Ah2 = pa_h[2*ks+1], Ah3 = pb_h[2*ks+1];
            uint32_t Al0 = pa_l[2*ks], Al1 = pb_l[2*ks], Al2 = pa_l[2*ks+1], Al3 = pb_l[2*ks+1];
            #pragma unroll
            for (int nt = 0; nt < 8; nt++) {
                int n = nt*8 + fr8;
                uint32_t Bh0 = sm[VH + n*36 + kc], Bh1 = sm[VH + n*36 + kc + 4];
                uint32_t Bl0 = sm[VL + n*36 + kc], Bl1 = sm[VL + n*36 + kc + 4];
                MMA_BF16(o[nt], Ah0,Ah1,Ah2,Ah3, Bh0,Bh1);
                MMA_BF16(o[nt], Ah0,Ah1,Ah2,Ah3, Bl0,Bl1);
                MMA_BF16(o[nt], Al0,Al1,Al2,Al3, Bh0,Bh1);
            }
        }
    }

    // ---- Epilogue ----
    {
        float inv0 = 1.f / l0, inv1 = 1.f / l1;
        #pragma unroll
        for (int nt = 0; nt < 8; nt++) {
            int col = h*64 + nt*8 + 2*fq;
            *(float2*)&out[(size_t)warp_row*HID + col] =
                make_float2(o[nt][0]*inv0, o[nt][1]*inv0);
            *(float2*)&out[(size_t)(warp_row+8)*HID + col] =
                make_float2(o[nt][2]*inv1, o[nt][3]*inv1);
        }
    }
}

// ----------------------------------------------------------------------------
extern "C" void kernel_launch(void* const* d_in, const int* in_sizes, int n_in,
                              void* d_out, int out_size)
{
    const float* x  = (const float*)d_in[0];
    const float* Wq = (const float*)d_in[1];
    const float* Wk = (const float*)d_in[2];
    const float* Wv = (const float*)d_in[3];
    float* out = (float*)d_out;

    split_prep<<<512, 256>>>(x, Wq, Wk, Wv);
    qkv_mma<<<dim3(24, 16), 256>>>();
    attn_mma<<<dim3(16, 16), 256>>>(out);
}

// round 9
// speedup vs baseline: 3.5921x; 1.2958x over previous
#include <cuda_runtime.h>
#include <cuda_fp16.h>
#include <cstdint>

// ============================================================================
// Round 7: fp16-split 2-pass mma.sync everywhere (tcgen05 unavailable: harness
// builds for sm_103 base target). QKV: xh@(Wh+Wl). Attn: Qh@(Kh+Kl),
// Ph@(Vh+Vl). P/Q/x lo-planes eliminated.
// ============================================================================

#define SEQ 2048
#define HID 1024
#define KVD 256
#define SCALE 0.03125f

__device__ __align__(16) __half g_xh[SEQ*HID];
__device__ __align__(16) __half g_wh[1536*HID], g_wl[1536*HID];
__device__ __align__(16) __half g_Qh[SEQ*HID];
__device__ __align__(16) __half g_Kh[SEQ*KVD],  g_Kl[SEQ*KVD];
__device__ __align__(16) __half g_Vth[KVD*SEQ], g_Vtl[KVD*SEQ];  // V^T [d][seq]

__device__ __forceinline__ void split2h(float v, __half* h, __half* l) {
    __half hh = __float2half_rn(v);
    *h = hh;
    *l = __float2half_rn(v - __half2float(hh));
}

#define MMA_F16(c, a0,a1,a2,a3, b0,b1) \
    asm volatile("mma.sync.aligned.m16n8k16.row.col.f32.f16.f16.f32 " \
        "{%0,%1,%2,%3}, {%4,%5,%6,%7}, {%8,%9}, {%0,%1,%2,%3};" \
        : "+f"((c)[0]), "+f"((c)[1]), "+f"((c)[2]), "+f"((c)[3]) \
        : "r"(a0), "r"(a1), "r"(a2), "r"(a3), "r"(b0), "r"(b1))

// ----------------------------------------------------------------------------
// Prep: x -> fp16 hi plane; W -> fp16 hi+lo planes.
// ----------------------------------------------------------------------------
__global__ void split_prep(const float* __restrict__ x, const float* __restrict__ Wq,
                           const float* __restrict__ Wk, const float* __restrict__ Wv)
{
    const int stride = gridDim.x * blockDim.x;
    const int t0 = blockIdx.x * blockDim.x + threadIdx.x;

    for (int i4 = t0; i4 < (SEQ*HID)/4; i4 += stride) {
        float4 v = ((const float4*)x)[i4];
        __half2 a = __floats2half2_rn(v.x, v.y);
        __half2 b = __floats2half2_rn(v.z, v.w);
        ((uint2*)g_xh)[i4] = make_uint2(*(uint32_t*)&a, *(uint32_t*)&b);
    }
    for (int i4 = t0; i4 < (1536*HID)/4; i4 += stride) {
        int i = i4 * 4;
        int r = i >> 10;
        float4 v;
        if (r < 1024)      v = *(const float4*)(Wq + i);
        else if (r < 1280) v = *(const float4*)(Wk + i - 1024*1024);
        else               v = *(const float4*)(Wv + i - 1280*1024);
        __half h0,l0,h1,l1,h2,l2,h3,l3;
        split2h(v.x,&h0,&l0); split2h(v.y,&h1,&l1);
        split2h(v.z,&h2,&l2); split2h(v.w,&h3,&l3);
        __half2 hA; hA.x=h0; hA.y=h1;
        __half2 hB; hB.x=h2; hB.y=h3;
        __half2 lA; lA.x=l0; lA.y=l1;
        __half2 lB; lB.x=l2; lB.y=l3;
        ((uint2*)g_wh)[i4] = make_uint2(*(uint32_t*)&hA, *(uint32_t*)&hB);
        ((uint2*)g_wl)[i4] = make_uint2(*(uint32_t*)&lA, *(uint32_t*)&lB);
    }
}

// ----------------------------------------------------------------------------
// QKV GEMM: [2048 x 1536] = x @ Wcat^T. BM=128, BN=64, BK=32, 8 warps (4x2),
// warp tile 32x32, 2-pass fp16 mma (xh*Wh + xh*Wl).
// ----------------------------------------------------------------------------
__global__ __launch_bounds__(256)
void qkv_mma()
{
    __shared__ uint32_t sAh[128*20], sBh[64*20], sBl[64*20];
    const int tid = threadIdx.x, lane = tid & 31, warp = tid >> 5;
    const int m0 = blockIdx.y * 128, n0 = blockIdx.x * 64;
    const int wm = warp >> 1, wn = warp & 1;

    float c[2][4][4];
    #pragma unroll
    for (int a = 0; a < 2; a++)
        #pragma unroll
        for (int b = 0; b < 4; b++)
            #pragma unroll
            for (int d = 0; d < 4; d++) c[a][b][d] = 0.f;

    const int ar = tid >> 1, ac = (tid & 1) * 8;
    const int br = tid >> 2, bc = (tid & 3) * 4;
    const __half* xh = g_xh + (size_t)(m0 + ar) * HID;
    const __half* wh = g_wh + (size_t)(n0 + br) * HID;
    const __half* wl = g_wl + (size_t)(n0 + br) * HID;

    for (int k0 = 0; k0 < HID; k0 += 32) {
        uint4 vah0 = *(const uint4*)(xh + k0 + ac*2);
        uint4 vah1 = *(const uint4*)(xh + k0 + ac*2 + 8);
        uint4 vbh  = *(const uint4*)(wh + k0 + bc*2);
        uint4 vbl  = *(const uint4*)(wl + k0 + bc*2);
        __syncthreads();
        *(uint4*)&sAh[ar*20 + ac]     = vah0;
        *(uint4*)&sAh[ar*20 + ac + 4] = vah1;
        *(uint4*)&sBh[br*20 + bc] = vbh;
        *(uint4*)&sBl[br*20 + bc] = vbl;
        __syncthreads();
        #pragma unroll
        for (int ks = 0; ks < 2; ks++) {
            const int kc = ks*8 + (lane & 3);
            uint32_t Ah[2][4];
            #pragma unroll
            for (int mt = 0; mt < 2; mt++) {
                int r = wm*32 + mt*16 + (lane >> 2);
                Ah[mt][0] = sAh[r*20 + kc];       Ah[mt][1] = sAh[(r+8)*20 + kc];
                Ah[mt][2] = sAh[r*20 + kc + 4];   Ah[mt][3] = sAh[(r+8)*20 + kc + 4];
            }
            #pragma unroll
            for (int nt = 0; nt < 4; nt++) {
                int n = wn*32 + nt*8 + (lane >> 2);
                uint32_t Bh0 = sBh[n*20 + kc], Bh1 = sBh[n*20 + kc + 4];
                uint32_t Bl0 = sBl[n*20 + kc], Bl1 = sBl[n*20 + kc + 4];
                #pragma unroll
                for (int mt = 0; mt < 2; mt++) {
                    MMA_F16(c[mt][nt], Ah[mt][0],Ah[mt][1],Ah[mt][2],Ah[mt][3], Bh0, Bh1);
                    MMA_F16(c[mt][nt], Ah[mt][0],Ah[mt][1],Ah[mt][2],Ah[mt][3], Bl0, Bl1);
                }
            }
        }
    }

    // Epilogue: Q hi-only (scaled); K hi/lo; V hi/lo transposed.
    #pragma unroll
    for (int mt = 0; mt < 2; mt++) {
        int r0 = m0 + wm*32 + mt*16 + (lane >> 2);
        #pragma unroll
        for (int nt = 0; nt < 4; nt++) {
            int col = n0 + wn*32 + nt*8 + 2*(lane & 3);
            float v0 = c[mt][nt][0], v1 = c[mt][nt][1];
            float v2 = c[mt][nt][2], v3 = c[mt][nt][3];
            if (n0 < 1024) {
                __half2 p0 = __floats2half2_rn(v0*SCALE, v1*SCALE);
                __half2 p1 = __floats2half2_rn(v2*SCALE, v3*SCALE);
                *(__half2*)&g_Qh[(size_t)r0*HID + col]     = p0;
                *(__half2*)&g_Qh[(size_t)(r0+8)*HID + col] = p1;
            } else if (n0 < 1280) {
                int kc2 = col - 1024;
                __half h0,l0,h1,l1,h2,l2,h3,l3;
                split2h(v0,&h0,&l0); split2h(v1,&h1,&l1);
                split2h(v2,&h2,&l2); split2h(v3,&h3,&l3);
                __half2 ph0; ph0.x = h0; ph0.y = h1;
                __half2 pl0; pl0.x = l0; pl0.y = l1;
                __half2 ph1; ph1.x = h2; ph1.y = h3;
                __half2 pl1; pl1.x = l2; pl1.y = l3;
                *(__half2*)&g_Kh[(size_t)r0*KVD + kc2]     = ph0;
                *(__half2*)&g_Kl[(size_t)r0*KVD + kc2]     = pl0;
                *(__half2*)&g_Kh[(size_t)(r0+8)*KVD + kc2] = ph1;
                *(__half2*)&g_Kl[(size_t)(r0+8)*KVD + kc2] = pl1;
            } else {
                int vc = col - 1280;
                __half h, l;
                split2h(v0,&h,&l); g_Vth[(size_t)vc*SEQ + r0]       = h; g_Vtl[(size_t)vc*SEQ + r0]       = l;
                split2h(v1,&h,&l); g_Vth[(size_t)(vc+1)*SEQ + r0]   = h; g_Vtl[(size_t)(vc+1)*SEQ + r0]   = l;
                split2h(v2,&h,&l); g_Vth[(size_t)vc*SEQ + r0+8]     = h; g_Vtl[(size_t)vc*SEQ + r0+8]     = l;
                split2h(v3,&h,&l); g_Vth[(size_t)(vc+1)*SEQ + r0+8] = h; g_Vtl[(size_t)(vc+1)*SEQ + r0+8] = l;
            }
        }
    }
}

// ----------------------------------------------------------------------------
// Attention: Br=128 (8 warps x 16 rows, full 64-key width per warp), Bc=64.
// FA2-style, P/softmax in registers. 2-pass fp16: Qh@(Kh+Kl), Ph@(Vh+Vl).
// smem u32: KH[64*36] KL[64*36] VH[64*36] VL[64*36]
// ----------------------------------------------------------------------------
#define KH 0
#define KL 2304
#define VH 4608
#define VL 6912

__global__ __launch_bounds__(256)
void attn_mma(float* __restrict__ out)
{
    __shared__ uint32_t sm[9216];

    const int tid = threadIdx.x, lane = tid & 31, w = tid >> 5;
    const int h  = blockIdx.y;
    const int qt = gridDim.x - 1 - blockIdx.x;     // longest first
    const int q0 = qt * 128;
    const int kvh = h >> 2;
    const int fq = lane & 3, fr8 = lane >> 2;
    const int warp_row = q0 + w*16 + fr8;

    // ---- Stage Q hi, read fragments ----
    {
        const int row = tid >> 1, half = (tid & 1) * 16;
        const __half* qh = g_Qh + (size_t)(q0 + row) * HID + h*64 + half*2;
        #pragma unroll
        for (int g = 0; g < 4; g++)
            *(uint4*)&sm[row*36 + half + g*4] = *(const uint4*)(qh + g*8);
    }
    __syncthreads();

    uint32_t qf[4][4];
    {
        const int r0 = w*16 + fr8;
        #pragma unroll
        for (int ks = 0; ks < 4; ks++) {
            int kc = ks*8 + fq;
            qf[ks][0] = sm[r0*36 + kc];     qf[ks][1] = sm[(r0+8)*36 + kc];
            qf[ks][2] = sm[r0*36 + kc + 4]; qf[ks][3] = sm[(r0+8)*36 + kc + 4];
        }
    }

    float o[8][4];
    #pragma unroll
    for (int nt = 0; nt < 8; nt++)
        #pragma unroll
        for (int j = 0; j < 4; j++) o[nt][j] = 0.f;
    float m0 = -1e30f, m1 = -1e30f, l0 = 0.f, l1 = 0.f;

    const int ldr = tid >> 2, seg = tid & 3;
    const int ktmax = 2*qt + 1;

    for (int kt = 0; kt <= ktmax; kt++) {
        const int k0 = kt * 64;
        __syncthreads();

        // Load K hi/lo [key][dpack], V^T hi/lo [d][keypack]
        {
            const __half* kh = g_Kh + (size_t)(k0 + ldr) * KVD + kvh*64 + seg*16;
            const __half* kl = g_Kl + (size_t)(k0 + ldr) * KVD + kvh*64 + seg*16;
            *(uint4*)&sm[KH + ldr*36 + seg*8]     = *(const uint4*)kh;
            *(uint4*)&sm[KH + ldr*36 + seg*8 + 4] = *(const uint4*)(kh + 8);
            *(uint4*)&sm[KL + ldr*36 + seg*8]     = *(const uint4*)kl;
            *(uint4*)&sm[KL + ldr*36 + seg*8 + 4] = *(const uint4*)(kl + 8);
            const __half* vh = g_Vth + (size_t)(kvh*64 + ldr) * SEQ + k0 + seg*16;
            const __half* vl = g_Vtl + (size_t)(kvh*64 + ldr) * SEQ + k0 + seg*16;
            *(uint4*)&sm[VH + ldr*36 + seg*8]     = *(const uint4*)vh;
            *(uint4*)&sm[VH + ldr*36 + seg*8 + 4] = *(const uint4*)(vh + 8);
            *(uint4*)&sm[VL + ldr*36 + seg*8]     = *(const uint4*)vl;
            *(uint4*)&sm[VL + ldr*36 + seg*8 + 4] = *(const uint4*)(vl + 8);
        }
        __syncthreads();

        if (k0 > q0 + w*16 + 15) continue;   // warp fully above causal boundary

        // ---- Phase 1: S = Qh @ (Kh + Kl)^T ----
        float s4[8][4];
        #pragma unroll
        for (int nt = 0; nt < 8; nt++)
            #pragma unroll
            for (int j = 0; j < 4; j++) s4[nt][j] = 0.f;
        #pragma unroll
        for (int ks = 0; ks < 4; ks++) {
            const int kc = ks*8 + fq;
            #pragma unroll
            for (int nt = 0; nt < 8; nt++) {
                int n = nt*8 + fr8;
                uint32_t Bh0 = sm[KH + n*36 + kc], Bh1 = sm[KH + n*36 + kc + 4];
                uint32_t Bl0 = sm[KL + n*36 + kc], Bl1 = sm[KL + n*36 + kc + 4];
                MMA_F16(s4[nt], qf[ks][0],qf[ks][1],qf[ks][2],qf[ks][3], Bh0,Bh1);
                MMA_F16(s4[nt], qf[ks][0],qf[ks][1],qf[ks][2],qf[ks][3], Bl0,Bl1);
            }
        }

        // Causal mask near the diagonal
        if (k0 + 63 > warp_row) {
            #pragma unroll
            for (int nt = 0; nt < 8; nt++) {
                int c0 = k0 + nt*8 + 2*fq;
                if (c0     > warp_row    ) s4[nt][0] = -1e30f;
                if (c0 + 1 > warp_row    ) s4[nt][1] = -1e30f;
                if (c0     > warp_row + 8) s4[nt][2] = -1e30f;
                if (c0 + 1 > warp_row + 8) s4[nt][3] = -1e30f;
            }
        }

        // ---- Warp-local online softmax ----
        float t0 = -1e30f, t1 = -1e30f;
        #pragma unroll
        for (int nt = 0; nt < 8; nt++) {
            t0 = fmaxf(t0, fmaxf(s4[nt][0], s4[nt][1]));
            t1 = fmaxf(t1, fmaxf(s4[nt][2], s4[nt][3]));
        }
        t0 = fmaxf(t0, __shfl_xor_sync(0xffffffffu, t0, 1));
        t0 = fmaxf(t0, __shfl_xor_sync(0xffffffffu, t0, 2));
        t1 = fmaxf(t1, __shfl_xor_sync(0xffffffffu, t1, 1));
        t1 = fmaxf(t1, __shfl_xor_sync(0xffffffffu, t1, 2));
        float mn0 = fmaxf(m0, t0), mn1 = fmaxf(m1, t1);
        float a0 = __expf(m0 - mn0), a1 = __expf(m1 - mn1);
        m0 = mn0; m1 = mn1;

        // exp + pack P (hi only) into A-fragments
        uint32_t pa[8], pb[8];
        float ls0 = 0.f, ls1 = 0.f;
        #pragma unroll
        for (int nt = 0; nt < 8; nt++) {
            float p0 = __expf(s4[nt][0] - mn0);
            float p1 = __expf(s4[nt][1] - mn0);
            float p2 = __expf(s4[nt][2] - mn1);
            float p3 = __expf(s4[nt][3] - mn1);
            ls0 += p0 + p1; ls1 += p2 + p3;
            __half2 hp0 = __floats2half2_rn(p0, p1);
            __half2 hp1 = __floats2half2_rn(p2, p3);
            pa[nt] = *(uint32_t*)&hp0;
            pb[nt] = *(uint32_t*)&hp1;
        }
        ls0 += __shfl_xor_sync(0xffffffffu, ls0, 1);
        ls0 += __shfl_xor_sync(0xffffffffu, ls0, 2);
        ls1 += __shfl_xor_sync(0xffffffffu, ls1, 1);
        ls1 += __shfl_xor_sync(0xffffffffu, ls1, 2);
        l0 = l0*a0 + ls0; l1 = l1*a1 + ls1;

        // rescale O
        #pragma unroll
        for (int nt = 0; nt < 8; nt++) {
            o[nt][0] *= a0; o[nt][1] *= a0;
            o[nt][2] *= a1; o[nt][3] *= a1;
        }

        // ---- Phase 2: O += Ph @ (Vh + Vl) ----
        #pragma unroll
        for (int ks = 0; ks < 4; ks++) {
            const int kc = ks*8 + fq;
            uint32_t A0 = pa[2*ks], A1 = pb[2*ks], A2 = pa[2*ks+1], A3 = pb[2*ks+1];
            #pragma unroll
            for (int nt = 0; nt < 8; nt++) {
                int n = nt*8 + fr8;
                uint32_t Bh0 = sm[VH + n*36 + kc], Bh1 = sm[VH + n*36 + kc + 4];
                uint32_t Bl0 = sm[VL + n*36 + kc], Bl1 = sm[VL + n*36 + kc + 4];
                MMA_F16(o[nt], A0,A1,A2,A3, Bh0,Bh1);
                MMA_F16(o[nt], A0,A1,A2,A3, Bl0,Bl1);
            }
        }
    }

    // ---- Epilogue ----
    {
        float inv0 = 1.f / l0, inv1 = 1.f / l1;
        #pragma unroll
        for (int nt = 0; nt < 8; nt++) {
            int col = h*64 + nt*8 + 2*fq;
            *(float2*)&out[(size_t)warp_row*HID + col] =
                make_float2(o[nt][0]*inv0, o[nt][1]*inv0);
            *(float2*)&out[(size_t)(warp_row+8)*HID + col] =
                make_float2(o[nt][2]*inv1, o[nt][3]*inv1);
        }
    }
}

// ----------------------------------------------------------------------------
extern "C" void kernel_launch(void* const* d_in, const int* in_sizes, int n_in,
                              void* d_out, int out_size)
{
    const float* x  = (const float*)d_in[0];
    const float* Wq = (const float*)d_in[1];
    const float* Wk = (const float*)d_in[2];
    const float* Wv = (const float*)d_in[3];
    float* out = (float*)d_out;

    split_prep<<<512, 256>>>(x, Wq, Wk, Wv);
    qkv_mma<<<dim3(24, 16), 256>>>();
    attn_mma<<<dim3(16, 16), 256>>>(out);
}

// round 11
// speedup vs baseline: 5.2078x; 1.4498x over previous
#include <cuda_runtime.h>
#include <cuda_fp16.h>
#include <cstdint>

// ============================================================================
// Round 11 (= Round 10 resubmit after infra failure): fully single-pass fp16
// mma.sync. QKV = xh@Wh, S = Qh@Kh, O = Ph@Vh. All lo planes eliminated;
// attention smem 18KB.
// ============================================================================

#define SEQ 2048
#define HID 1024
#define KVD 256
#define SCALE 0.03125f

__device__ __align__(16) __half g_xh[SEQ*HID];
__device__ __align__(16) __half g_wh[1536*HID];
__device__ __align__(16) __half g_Qh[SEQ*HID];
__device__ __align__(16) __half g_Kh[SEQ*KVD];
__device__ __align__(16) __half g_Vth[KVD*SEQ];   // V^T [d][seq]

#define MMA_F16(c, a0,a1,a2,a3, b0,b1) \
    asm volatile("mma.sync.aligned.m16n8k16.row.col.f32.f16.f16.f32 " \
        "{%0,%1,%2,%3}, {%4,%5,%6,%7}, {%8,%9}, {%0,%1,%2,%3};" \
        : "+f"((c)[0]), "+f"((c)[1]), "+f"((c)[2]), "+f"((c)[3]) \
        : "r"(a0), "r"(a1), "r"(a2), "r"(a3), "r"(b0), "r"(b1))

// ----------------------------------------------------------------------------
// Prep: x, W -> fp16 hi planes.
// ----------------------------------------------------------------------------
__global__ void split_prep(const float* __restrict__ x, const float* __restrict__ Wq,
                           const float* __restrict__ Wk, const float* __restrict__ Wv)
{
    const int stride = gridDim.x * blockDim.x;
    const int t0 = blockIdx.x * blockDim.x + threadIdx.x;

    for (int i4 = t0; i4 < (SEQ*HID)/4; i4 += stride) {
        float4 v = ((const float4*)x)[i4];
        __half2 a = __floats2half2_rn(v.x, v.y);
        __half2 b = __floats2half2_rn(v.z, v.w);
        ((uint2*)g_xh)[i4] = make_uint2(*(uint32_t*)&a, *(uint32_t*)&b);
    }
    for (int i4 = t0; i4 < (1536*HID)/4; i4 += stride) {
        int i = i4 * 4;
        int r = i >> 10;
        float4 v;
        if (r < 1024)      v = *(const float4*)(Wq + i);
        else if (r < 1280) v = *(const float4*)(Wk + i - 1024*1024);
        else               v = *(const float4*)(Wv + i - 1280*1024);
        __half2 a = __floats2half2_rn(v.x, v.y);
        __half2 b = __floats2half2_rn(v.z, v.w);
        ((uint2*)g_wh)[i4] = make_uint2(*(uint32_t*)&a, *(uint32_t*)&b);
    }
}

// ----------------------------------------------------------------------------
// QKV GEMM: [2048 x 1536] = x @ Wcat^T. BM=128, BN=64, BK=32, 8 warps (4x2),
// warp tile 32x32, single-pass fp16 mma.
// ----------------------------------------------------------------------------
__global__ __launch_bounds__(256)
void qkv_mma()
{
    __shared__ uint32_t sAh[128*20], sBh[64*20];
    const int tid = threadIdx.x, lane = tid & 31, warp = tid >> 5;
    const int m0 = blockIdx.y * 128, n0 = blockIdx.x * 64;
    const int wm = warp >> 1, wn = warp & 1;

    float c[2][4][4];
    #pragma unroll
    for (int a = 0; a < 2; a++)
        #pragma unroll
        for (int b = 0; b < 4; b++)
            #pragma unroll
            for (int d = 0; d < 4; d++) c[a][b][d] = 0.f;

    const int ar = tid >> 1, ac = (tid & 1) * 8;
    const int br = tid >> 2, bc = (tid & 3) * 4;
    const __half* xh = g_xh + (size_t)(m0 + ar) * HID;
    const __half* wh = g_wh + (size_t)(n0 + br) * HID;

    for (int k0 = 0; k0 < HID; k0 += 32) {
        uint4 vah0 = *(const uint4*)(xh + k0 + ac*2);
        uint4 vah1 = *(const uint4*)(xh + k0 + ac*2 + 8);
        uint4 vbh  = *(const uint4*)(wh + k0 + bc*2);
        __syncthreads();
        *(uint4*)&sAh[ar*20 + ac]     = vah0;
        *(uint4*)&sAh[ar*20 + ac + 4] = vah1;
        *(uint4*)&sBh[br*20 + bc] = vbh;
        __syncthreads();
        #pragma unroll
        for (int ks = 0; ks < 2; ks++) {
            const int kc = ks*8 + (lane & 3);
            uint32_t Ah[2][4];
            #pragma unroll
            for (int mt = 0; mt < 2; mt++) {
                int r = wm*32 + mt*16 + (lane >> 2);
                Ah[mt][0] = sAh[r*20 + kc];       Ah[mt][1] = sAh[(r+8)*20 + kc];
                Ah[mt][2] = sAh[r*20 + kc + 4];   Ah[mt][3] = sAh[(r+8)*20 + kc + 4];
            }
            #pragma unroll
            for (int nt = 0; nt < 4; nt++) {
                int n = wn*32 + nt*8 + (lane >> 2);
                uint32_t Bh0 = sBh[n*20 + kc], Bh1 = sBh[n*20 + kc + 4];
                #pragma unroll
                for (int mt = 0; mt < 2; mt++)
                    MMA_F16(c[mt][nt], Ah[mt][0],Ah[mt][1],Ah[mt][2],Ah[mt][3], Bh0, Bh1);
            }
        }
    }

    // Epilogue: Q (scaled) / K row-major hi; V transposed hi.
    #pragma unroll
    for (int mt = 0; mt < 2; mt++) {
        int r0 = m0 + wm*32 + mt*16 + (lane >> 2);
        #pragma unroll
        for (int nt = 0; nt < 4; nt++) {
            int col = n0 + wn*32 + nt*8 + 2*(lane & 3);
            float v0 = c[mt][nt][0], v1 = c[mt][nt][1];
            float v2 = c[mt][nt][2], v3 = c[mt][nt][3];
            if (n0 < 1024) {
                __half2 p0 = __floats2half2_rn(v0*SCALE, v1*SCALE);
                __half2 p1 = __floats2half2_rn(v2*SCALE, v3*SCALE);
                *(__half2*)&g_Qh[(size_t)r0*HID + col]     = p0;
                *(__half2*)&g_Qh[(size_t)(r0+8)*HID + col] = p1;
            } else if (n0 < 1280) {
                int kc2 = col - 1024;
                __half2 p0 = __floats2half2_rn(v0, v1);
                __half2 p1 = __floats2half2_rn(v2, v3);
                *(__half2*)&g_Kh[(size_t)r0*KVD + kc2]     = p0;
                *(__half2*)&g_Kh[(size_t)(r0+8)*KVD + kc2] = p1;
            } else {
                int vc = col - 1280;
                g_Vth[(size_t)vc*SEQ + r0]       = __float2half_rn(v0);
                g_Vth[(size_t)(vc+1)*SEQ + r0]   = __float2half_rn(v1);
                g_Vth[(size_t)vc*SEQ + r0+8]     = __float2half_rn(v2);
                g_Vth[(size_t)(vc+1)*SEQ + r0+8] = __float2half_rn(v3);
            }
        }
    }
}

// ----------------------------------------------------------------------------
// Attention: Br=128 (8 warps x 16 rows, full 64-key width per warp), Bc=64.
// FA2-style, P/softmax in registers. Single-pass fp16: Qh@Kh, Ph@Vh.
// smem u32: KH[64*36]=2304, VH[64*36]=2304 (18KB); Q staged over both at entry.
// ----------------------------------------------------------------------------
#define KH 0
#define VH 2304

__global__ __launch_bounds__(256)
void attn_mma(float* __restrict__ out)
{
    __shared__ uint32_t sm[4608];

    const int tid = threadIdx.x, lane = tid & 31, w = tid >> 5;
    const int h  = blockIdx.y;
    const int qt = gridDim.x - 1 - blockIdx.x;     // longest first
    const int q0 = qt * 128;
    const int kvh = h >> 2;
    const int fq = lane & 3, fr8 = lane >> 2;
    const int warp_row = q0 + w*16 + fr8;

    // ---- Stage Q hi, read fragments ----
    {
        const int row = tid >> 1, half = (tid & 1) * 16;
        const __half* qh = g_Qh + (size_t)(q0 + row) * HID + h*64 + half*2;
        #pragma unroll
        for (int g = 0; g < 4; g++)
            *(uint4*)&sm[row*36 + half + g*4] = *(const uint4*)(qh + g*8);
    }
    __syncthreads();

    uint32_t qf[4][4];
    {
        const int r0 = w*16 + fr8;
        #pragma unroll
        for (int ks = 0; ks < 4; ks++) {
            int kc = ks*8 + fq;
            qf[ks][0] = sm[r0*36 + kc];     qf[ks][1] = sm[(r0+8)*36 + kc];
            qf[ks][2] = sm[r0*36 + kc + 4]; qf[ks][3] = sm[(r0+8)*36 + kc + 4];
        }
    }

    float o[8][4];
    #pragma unroll
    for (int nt = 0; nt < 8; nt++)
        #pragma unroll
        for (int j = 0; j < 4; j++) o[nt][j] = 0.f;
    float m0 = -1e30f, m1 = -1e30f, l0 = 0.f, l1 = 0.f;

    const int ldr = tid >> 2, seg = tid & 3;
    const int ktmax = 2*qt + 1;

    for (int kt = 0; kt <= ktmax; kt++) {
        const int k0 = kt * 64;
        __syncthreads();

        // Load K [key][dpack], V^T [d][keypack]
        {
            const __half* kh = g_Kh + (size_t)(k0 + ldr) * KVD + kvh*64 + seg*16;
            *(uint4*)&sm[KH + ldr*36 + seg*8]     = *(const uint4*)kh;
            *(uint4*)&sm[KH + ldr*36 + seg*8 + 4] = *(const uint4*)(kh + 8);
            const __half* vh = g_Vth + (size_t)(kvh*64 + ldr) * SEQ + k0 + seg*16;
            *(uint4*)&sm[VH + ldr*36 + seg*8]     = *(const uint4*)vh;
            *(uint4*)&sm[VH + ldr*36 + seg*8 + 4] = *(const uint4*)(vh + 8);
        }
        __syncthreads();

        if (k0 > q0 + w*16 + 15) continue;   // warp fully above causal boundary

        // ---- Phase 1: S = Qh @ Kh^T ----
        float s4[8][4];
        #pragma unroll
        for (int nt = 0; nt < 8; nt++)
            #pragma unroll
            for (int j = 0; j < 4; j++) s4[nt][j] = 0.f;
        #pragma unroll
        for (int ks = 0; ks < 4; ks++) {
            const int kc = ks*8 + fq;
            #pragma unroll
            for (int nt = 0; nt < 8; nt++) {
                int n = nt*8 + fr8;
                uint32_t Bh0 = sm[KH + n*36 + kc], Bh1 = sm[KH + n*36 + kc + 4];
                MMA_F16(s4[nt], qf[ks][0],qf[ks][1],qf[ks][2],qf[ks][3], Bh0,Bh1);
            }
        }

        // Causal mask near the diagonal
        if (k0 + 63 > warp_row) {
            #pragma unroll
            for (int nt = 0; nt < 8; nt++) {
                int c0 = k0 + nt*8 + 2*fq;
                if (c0     > warp_row    ) s4[nt][0] = -1e30f;
                if (c0 + 1 > warp_row    ) s4[nt][1] = -1e30f;
                if (c0     > warp_row + 8) s4[nt][2] = -1e30f;
                if (c0 + 1 > warp_row + 8) s4[nt][3] = -1e30f;
            }
        }

        // ---- Warp-local online softmax ----
        float t0 = -1e30f, t1 = -1e30f;
        #pragma unroll
        for (int nt = 0; nt < 8; nt++) {
            t0 = fmaxf(t0, fmaxf(s4[nt][0], s4[nt][1]));
            t1 = fmaxf(t1, fmaxf(s4[nt][2], s4[nt][3]));
        }
        t0 = fmaxf(t0, __shfl_xor_sync(0xffffffffu, t0, 1));
        t0 = fmaxf(t0, __shfl_xor_sync(0xffffffffu, t0, 2));
        t1 = fmaxf(t1, __shfl_xor_sync(0xffffffffu, t1, 1));
        t1 = fmaxf(t1, __shfl_xor_sync(0xffffffffu, t1, 2));
        float mn0 = fmaxf(m0, t0), mn1 = fmaxf(m1, t1);
        float a0 = __expf(m0 - mn0), a1 = __expf(m1 - mn1);
        m0 = mn0; m1 = mn1;

        // exp + pack P into A-fragments
        uint32_t pa[8], pb[8];
        float ls0 = 0.f, ls1 = 0.f;
        #pragma unroll
        for (int nt = 0; nt < 8; nt++) {
            float p0 = __expf(s4[nt][0] - mn0);
            float p1 = __expf(s4[nt][1] - mn0);
            float p2 = __expf(s4[nt][2] - mn1);
            float p3 = __expf(s4[nt][3] - mn1);
            ls0 += p0 + p1; ls1 += p2 + p3;
            __half2 hp0 = __floats2half2_rn(p0, p1);
            __half2 hp1 = __floats2half2_rn(p2, p3);
            pa[nt] = *(uint32_t*)&hp0;
            pb[nt] = *(uint32_t*)&hp1;
        }
        ls0 += __shfl_xor_sync(0xffffffffu, ls0, 1);
        ls0 += __shfl_xor_sync(0xffffffffu, ls0, 2);
        ls1 += __shfl_xor_sync(0xffffffffu, ls1, 1);
        ls1 += __shfl_xor_sync(0xffffffffu, ls1, 2);
        l0 = l0*a0 + ls0; l1 = l1*a1 + ls1;

        // rescale O
        #pragma unroll
        for (int nt = 0; nt < 8; nt++) {
            o[nt][0] *= a0; o[nt][1] *= a0;
            o[nt][2] *= a1; o[nt][3] *= a1;
        }

        // ---- Phase 2: O += Ph @ Vh ----
        #pragma unroll
        for (int ks = 0; ks < 4; ks++) {
            const int kc = ks*8 + fq;
            uint32_t A0 = pa[2*ks], A1 = pb[2*ks], A2 = pa[2*ks+1], A3 = pb[2*ks+1];
            #pragma unroll
            for (int nt = 0; nt < 8; nt++) {
                int n = nt*8 + fr8;
                uint32_t Bh0 = sm[VH + n*36 + kc], Bh1 = sm[VH + n*36 + kc + 4];
                MMA_F16(o[nt], A0,A1,A2,A3, Bh0,Bh1);
            }
        }
    }

    // ---- Epilogue ----
    {
        float inv0 = 1.f / l0, inv1 = 1.f / l1;
        #pragma unroll
        for (int nt = 0; nt < 8; nt++) {
            int col = h*64 + nt*8 + 2*fq;
            *(float2*)&out[(size_t)warp_row*HID + col] =
                make_float2(o[nt][0]*inv0, o[nt][1]*inv0);
            *(float2*)&out[(size_t)(warp_row+8)*HID + col] =
                make_float2(o[nt][2]*inv1, o[nt][3]*inv1);
        }
    }
}

// ----------------------------------------------------------------------------
extern "C" void kernel_launch(void* const* d_in, const int* in_sizes, int n_in,
                              void* d_out, int out_size)
{
    const float* x  = (const float*)d_in[0];
    const float* Wq = (const float*)d_in[1];
    const float* Wk = (const float*)d_in[2];
    const float* Wv = (const float*)d_in[3];
    float* out = (float*)d_out;

    split_prep<<<512, 256>>>(x, Wq, Wk, Wv);
    qkv_mma<<<dim3(24, 16), 256>>>();
    attn_mma<<<dim3(16, 16), 256>>>(out);
}

// round 15
// speedup vs baseline: 6.2120x; 1.1928x over previous
#include <cuda_runtime.h>
#include <cuda_fp16.h>
#include <cstdint>

// ============================================================================
// Round 12: single-pass fp16 mma.sync + cp.async 2-stage double buffering +
// ldmatrix fragment loads in both GEMM kernels. Arithmetic identical to R11.
// ============================================================================

#define SEQ 2048
#define HID 1024
#define KVD 256
#define SCALE 0.03125f

__device__ __align__(16) __half g_xh[SEQ*HID];
__device__ __align__(16) __half g_wh[1536*HID];
__device__ __align__(16) __half g_Qh[SEQ*HID];
__device__ __align__(16) __half g_Kh[SEQ*KVD];
__device__ __align__(16) __half g_Vth[KVD*SEQ];   // V^T [d][seq]

#define MMA_F16(c, a0,a1,a2,a3, b0,b1) \
    asm volatile("mma.sync.aligned.m16n8k16.row.col.f32.f16.f16.f32 " \
        "{%0,%1,%2,%3}, {%4,%5,%6,%7}, {%8,%9}, {%0,%1,%2,%3};" \
        : "+f"((c)[0]), "+f"((c)[1]), "+f"((c)[2]), "+f"((c)[3]) \
        : "r"(a0), "r"(a1), "r"(a2), "r"(a3), "r"(b0), "r"(b1))

#define LDSM4(r0,r1,r2,r3, a) \
    asm volatile("ldmatrix.sync.aligned.m8n8.x4.shared.b16 {%0,%1,%2,%3}, [%4];" \
        : "=r"(r0), "=r"(r1), "=r"(r2), "=r"(r3) : "r"(a))

#define CP16(dst, src) \
    asm volatile("cp.async.cg.shared.global [%0], [%1], 16;" :: "r"(dst), "l"(src) : "memory")
#define CPC()  asm volatile("cp.async.commit_group;" ::: "memory")
#define CPW1() asm volatile("cp.async.wait_group 1;" ::: "memory")
#define CPW0() asm volatile("cp.async.wait_group 0;" ::: "memory")

__device__ __forceinline__ uint32_t smaddr(const void* p) {
    uint32_t a;
    asm("{ .reg .u64 t; cvta.to.shared.u64 t, %1; cvt.u32.u64 %0, t; }"
        : "=r"(a) : "l"(p));
    return a;
}

// ----------------------------------------------------------------------------
// Prep: x, W -> fp16 planes.
// ----------------------------------------------------------------------------
__global__ void split_prep(const float* __restrict__ x, const float* __restrict__ Wq,
                           const float* __restrict__ Wk, const float* __restrict__ Wv)
{
    const int stride = gridDim.x * blockDim.x;
    const int t0 = blockIdx.x * blockDim.x + threadIdx.x;

    for (int i4 = t0; i4 < (SEQ*HID)/4; i4 += stride) {
        float4 v = ((const float4*)x)[i4];
        __half2 a = __floats2half2_rn(v.x, v.y);
        __half2 b = __floats2half2_rn(v.z, v.w);
        ((uint2*)g_xh)[i4] = make_uint2(*(uint32_t*)&a, *(uint32_t*)&b);
    }
    for (int i4 = t0; i4 < (1536*HID)/4; i4 += stride) {
        int i = i4 * 4;
        int r = i >> 10;
        float4 v;
        if (r < 1024)      v = *(const float4*)(Wq + i);
        else if (r < 1280) v = *(const float4*)(Wk + i - 1024*1024);
        else               v = *(const float4*)(Wv + i - 1280*1024);
        __half2 a = __floats2half2_rn(v.x, v.y);
        __half2 b = __floats2half2_rn(v.z, v.w);
        ((uint2*)g_wh)[i4] = make_uint2(*(uint32_t*)&a, *(uint32_t*)&b);
    }
}

// ----------------------------------------------------------------------------
// QKV GEMM: [2048 x 1536] = x @ Wcat^T. BM=128, BN=64, BK=32, 8 warps (4x2),
// warp tile 32x32. cp.async double buffered, ldmatrix fragments.
// Stage (u32): A 128x20=2560, B 64x20=1280 -> 3840 u32 = 15360 B per stage.
// ----------------------------------------------------------------------------
__global__ __launch_bounds__(256)
void qkv_mma()
{
    __shared__ uint32_t sq[2*3840];
    const int tid = threadIdx.x, lane = tid & 31, warp = tid >> 5;
    const int m0 = blockIdx.y * 128, n0 = blockIdx.x * 64;
    const int wm = warp >> 1, wn = warp & 1;
    const uint32_t smb = smaddr(sq);

    float c[2][4][4];
    #pragma unroll
    for (int a = 0; a < 2; a++)
        #pragma unroll
        for (int b = 0; b < 4; b++)
            #pragma unroll
            for (int d = 0; d < 4; d++) c[a][b][d] = 0.f;

    // load geometry (same data placement as R11)
    const int ar = tid >> 1, ac = (tid & 1) * 8;
    const int br = tid >> 2, bc = (tid & 3) * 4;
    const __half* xsrc = g_xh + (size_t)(m0 + ar) * HID + ac*2;
    const __half* wsrc = g_wh + (size_t)(n0 + br) * HID + bc*2;
    const uint32_t dA = smb + (ar*20 + ac)*4;
    const uint32_t dB = smb + 10240 + (br*20 + bc)*4;

    // ldmatrix per-lane offsets (bytes)
    const int arow = ((lane>>3)&1)*8 + (lane&7);
    const int ako  = ((lane>>4)&1)*16;
    const int brow = ((lane>>4)&1)*8 + (lane&7);
    const int bko  = ((lane>>3)&1)*16;
    const uint32_t aAddr = smb + (wm*32 + arow)*80 + ako;
    const uint32_t bAddr = smb + 10240 + (wn*32 + brow)*80 + bko;

    // prefetch tile 0
    {
        CP16(dA, xsrc); CP16(dA + 16, xsrc + 8);
        CP16(dB, wsrc);
        CPC();
    }

    for (int kt = 0; kt < 32; kt++) {
        const int s = kt & 1;
        const uint32_t soff = s * 15360;
        if (kt < 31) {
            const int k1 = (kt+1) * 32;
            const uint32_t so2 = (s^1) * 15360;
            CP16(dA + so2, xsrc + k1); CP16(dA + so2 + 16, xsrc + k1 + 8);
            CP16(dB + so2, wsrc + k1);
            CPC();
            CPW1();
        } else {
            CPW0();
        }
        __syncthreads();

        #pragma unroll
        for (int ks = 0; ks < 2; ks++) {
            uint32_t A0[4], A1[4];
            LDSM4(A0[0],A0[1],A0[2],A0[3], aAddr + soff + ks*32);
            LDSM4(A1[0],A1[1],A1[2],A1[3], aAddr + soff + 1280 + ks*32);
            #pragma unroll
            for (int ntp = 0; ntp < 2; ntp++) {
                uint32_t b0,b1,b2,b3;
                LDSM4(b0,b1,b2,b3, bAddr + soff + ntp*1280 + ks*32);
                MMA_F16(c[0][2*ntp],   A0[0],A0[1],A0[2],A0[3], b0,b1);
                MMA_F16(c[1][2*ntp],   A1[0],A1[1],A1[2],A1[3], b0,b1);
                MMA_F16(c[0][2*ntp+1], A0[0],A0[1],A0[2],A0[3], b2,b3);
                MMA_F16(c[1][2*ntp+1], A1[0],A1[1],A1[2],A1[3], b2,b3);
            }
        }
        __syncthreads();
    }

    // Epilogue: Q (scaled) / K row-major; V transposed.
    #pragma unroll
    for (int mt = 0; mt < 2; mt++) {
        int r0 = m0 + wm*32 + mt*16 + (lane >> 2);
        #pragma unroll
        for (int nt = 0; nt < 4; nt++) {
            int col = n0 + wn*32 + nt*8 + 2*(lane & 3);
            float v0 = c[mt][nt][0], v1 = c[mt][nt][1];
            float v2 = c[mt][nt][2], v3 = c[mt][nt][3];
            if (n0 < 1024) {
                __half2 p0 = __floats2half2_rn(v0*SCALE, v1*SCALE);
                __half2 p1 = __floats2half2_rn(v2*SCALE, v3*SCALE);
                *(__half2*)&g_Qh[(size_t)r0*HID + col]     = p0;
                *(__half2*)&g_Qh[(size_t)(r0+8)*HID + col] = p1;
            } else if (n0 < 1280) {
                int kc2 = col - 1024;
                __half2 p0 = __floats2half2_rn(v0, v1);
                __half2 p1 = __floats2half2_rn(v2, v3);
                *(__half2*)&g_Kh[(size_t)r0*KVD + kc2]     = p0;
                *(__half2*)&g_Kh[(size_t)(r0+8)*KVD + kc2] = p1;
            } else {
                int vc = col - 1280;
                g_Vth[(size_t)vc*SEQ + r0]       = __float2half_rn(v0);
                g_Vth[(size_t)(vc+1)*SEQ + r0]   = __float2half_rn(v1);
                g_Vth[(size_t)vc*SEQ + r0+8]     = __float2half_rn(v2);
                g_Vth[(size_t)(vc+1)*SEQ + r0+8] = __float2half_rn(v3);
            }
        }
    }
}

// ----------------------------------------------------------------------------
// Attention: Br=128 (8 warps x 16 rows, full 64-key width/warp), Bc=64.
// FA2-style register softmax. cp.async double buffered K/V, ldmatrix frags.
// Stage (u32): K 64x36=2304, V 64x36=2304 -> 4608 u32 = 18432 B per stage.
// ----------------------------------------------------------------------------
__global__ __launch_bounds__(256)
void attn_mma(float* __restrict__ out)
{
    __shared__ uint32_t sm[2*4608];

    const int tid = threadIdx.x, lane = tid & 31, w = tid >> 5;
    const int h  = blockIdx.y;
    const int qt = gridDim.x - 1 - blockIdx.x;     // longest first
    const int q0 = qt * 128;
    const int kvh = h >> 2;
    const int fq = lane & 3, fr8 = lane >> 2;
    const int warp_row = q0 + w*16 + fr8;
    const uint32_t smb = smaddr(sm);

    // ---- Stage Q (into stage-0 region), extract fragments via ldmatrix ----
    {
        const int row = tid >> 1, half = (tid & 1) * 16;
        const __half* qh = g_Qh + (size_t)(q0 + row) * HID + h*64 + half*2;
        #pragma unroll
        for (int g = 0; g < 4; g++)
            *(uint4*)&sm[row*36 + half + g*4] = *(const uint4*)(qh + g*8);
    }
    __syncthreads();

    uint32_t qf[4][4];
    {
        const int qrow = ((lane>>3)&1)*8 + (lane&7);
        const int qko  = ((lane>>4)&1)*16;
        const uint32_t qaddr = smb + (w*16 + qrow)*144 + qko;
        #pragma unroll
        for (int ks = 0; ks < 4; ks++)
            LDSM4(qf[ks][0],qf[ks][1],qf[ks][2],qf[ks][3], qaddr + ks*32);
    }
    __syncthreads();   // Q reads done before prefetch overwrites stage 0

    // cp.async geometry
    const int ldr = tid >> 2, seg = tid & 3;
    const uint32_t dK = smb + (ldr*36 + seg*8)*4;
    const uint32_t dV = smb + 9216 + (ldr*36 + seg*8)*4;
    const __half* ksrc = g_Kh  + (size_t)ldr * KVD + kvh*64 + seg*16;
    const __half* vsrc = g_Vth + (size_t)(kvh*64 + ldr) * SEQ + seg*16;

    // ldmatrix per-lane B offsets (bytes)
    const int brow = ((lane>>4)&1)*8 + (lane&7);
    const int bko  = ((lane>>3)&1)*16;
    const uint32_t kfrag = smb + brow*144 + bko;
    const uint32_t vfrag = smb + 9216 + brow*144 + bko;

    float o[8][4];
    #pragma unroll
    for (int nt = 0; nt < 8; nt++)
        #pragma unroll
        for (int j = 0; j < 4; j++) o[nt][j] = 0.f;
    float m0 = -1e30f, m1 = -1e30f, l0 = 0.f, l1 = 0.f;

    const int ktmax = 2*qt + 1;

    // prefetch tile 0 into stage 0
    {
        CP16(dK, ksrc); CP16(dK + 16, ksrc + 8);
        CP16(dV, vsrc); CP16(dV + 16, vsrc + 8);
        CPC();
    }

    for (int kt = 0; kt <= ktmax; kt++) {
        const int s = kt & 1;
        const int k0 = kt * 64;
        const uint32_t soff = s * 18432;

        if (kt < ktmax) {
            const uint32_t so2 = (s^1) * 18432;
            const int k1 = (kt+1) * 64;
            CP16(dK + so2, ksrc + (size_t)k1*KVD); CP16(dK + so2 + 16, ksrc + (size_t)k1*KVD + 8);
            CP16(dV + so2, vsrc + k1);             CP16(dV + so2 + 16, vsrc + k1 + 8);
            CPC();
            CPW1();
        } else {
            CPW0();
        }
        __syncthreads();

        if (k0 <= q0 + w*16 + 15) {
            // ---- Phase 1: S = Qh @ Kh^T ----
            float s4[8][4];
            #pragma unroll
            for (int nt = 0; nt < 8; nt++)
                #pragma unroll
                for (int j = 0; j < 4; j++) s4[nt][j] = 0.f;
            #pragma unroll
            for (int ks = 0; ks < 4; ks++) {
                #pragma unroll
                for (int ntp = 0; ntp < 4; ntp++) {
                    uint32_t b0,b1,b2,b3;
                    LDSM4(b0,b1,b2,b3, kfrag + soff + ntp*2304 + ks*32);
                    MMA_F16(s4[2*ntp],   qf[ks][0],qf[ks][1],qf[ks][2],qf[ks][3], b0,b1);
                    MMA_F16(s4[2*ntp+1], qf[ks][0],qf[ks][1],qf[ks][2],qf[ks][3], b2,b3);
                }
            }

            // Causal mask near the diagonal
            if (k0 + 63 > warp_row) {
                #pragma unroll
                for (int nt = 0; nt < 8; nt++) {
                    int c0 = k0 + nt*8 + 2*fq;
                    if (c0     > warp_row    ) s4[nt][0] = -1e30f;
                    if (c0 + 1 > warp_row    ) s4[nt][1] = -1e30f;
                    if (c0     > warp_row + 8) s4[nt][2] = -1e30f;
                    if (c0 + 1 > warp_row + 8) s4[nt][3] = -1e30f;
                }
            }

            // ---- Warp-local online softmax ----
            float t0 = -1e30f, t1 = -1e30f;
            #pragma unroll
            for (int nt = 0; nt < 8; nt++) {
                t0 = fmaxf(t0, fmaxf(s4[nt][0], s4[nt][1]));
                t1 = fmaxf(t1, fmaxf(s4[nt][2], s4[nt][3]));
            }
            t0 = fmaxf(t0, __shfl_xor_sync(0xffffffffu, t0, 1));
            t0 = fmaxf(t0, __shfl_xor_sync(0xffffffffu, t0, 2));
            t1 = fmaxf(t1, __shfl_xor_sync(0xffffffffu, t1, 1));
            t1 = fmaxf(t1, __shfl_xor_sync(0xffffffffu, t1, 2));
            float mn0 = fmaxf(m0, t0), mn1 = fmaxf(m1, t1);
            float a0 = __expf(m0 - mn0), a1 = __expf(m1 - mn1);
            m0 = mn0; m1 = mn1;

            // exp + pack P into A-fragments
            uint32_t pa[8], pb[8];
            float ls0 = 0.f, ls1 = 0.f;
            #pragma unroll
            for (int nt = 0; nt < 8; nt++) {
                float p0 = __expf(s4[nt][0] - mn0);
                float p1 = __expf(s4[nt][1] - mn0);
                float p2 = __expf(s4[nt][2] - mn1);
                float p3 = __expf(s4[nt][3] - mn1);
                ls0 += p0 + p1; ls1 += p2 + p3;
                __half2 hp0 = __floats2half2_rn(p0, p1);
                __half2 hp1 = __floats2half2_rn(p2, p3);
                pa[nt] = *(uint32_t*)&hp0;
                pb[nt] = *(uint32_t*)&hp1;
            }
            ls0 += __shfl_xor_sync(0xffffffffu, ls0, 1);
            ls0 += __shfl_xor_sync(0xffffffffu, ls0, 2);
            ls1 += __shfl_xor_sync(0xffffffffu, ls1, 1);
            ls1 += __shfl_xor_sync(0xffffffffu, ls1, 2);
            l0 = l0*a0 + ls0; l1 = l1*a1 + ls1;

            // rescale O
            #pragma unroll
            for (int nt = 0; nt < 8; nt++) {
                o[nt][0] *= a0; o[nt][1] *= a0;
                o[nt][2] *= a1; o[nt][3] *= a1;
            }

            // ---- Phase 2: O += Ph @ Vh ----
            #pragma unroll
            for (int ks = 0; ks < 4; ks++) {
                uint32_t A0 = pa[2*ks], A1 = pb[2*ks], A2 = pa[2*ks+1], A3 = pb[2*ks+1];
                #pragma unroll
                for (int ntp = 0; ntp < 4; ntp++) {
                    uint32_t b0,b1,b2,b3;
                    LDSM4(b0,b1,b2,b3, vfrag + soff + ntp*2304 + ks*32);
                    MMA_F16(o[2*ntp],   A0,A1,A2,A3, b0,b1);
                    MMA_F16(o[2*ntp+1], A0,A1,A2,A3, b2,b3);
                }
            }
        }
        __syncthreads();
    }

    // ---- Epilogue ----
    {
        float inv0 = 1.f / l0, inv1 = 1.f / l1;
        #pragma unroll
        for (int nt = 0; nt < 8; nt++) {
            int col = h*64 + nt*8 + 2*fq;
            *(float2*)&out[(size_t)warp_row*HID + col] =
                make_float2(o[nt][0]*inv0, o[nt][1]*inv0);
            *(float2*)&out[(size_t)(warp_row+8)*HID + col] =
                make_float2(o[nt][2]*inv1, o[nt][3]*inv1);
        }
    }
}

// ----------------------------------------------------------------------------
extern "C" void kernel_launch(void* const* d_in, const int* in_sizes, int n_in,
                              void* d_out, int out_size)
{
    const float* x  = (const float*)d_in[0];
    const float* Wq = (const float*)d_in[1];
    const float* Wk = (const float*)d_in[2];
    const float* Wv = (const float*)d_in[3];
    float* out = (float*)d_out;

    split_prep<<<1024, 256>>>(x, Wq, Wk, Wv);
    qkv_mma<<<dim3(24, 16), 256>>>();
    attn_mma<<<dim3(16, 16), 256>>>(out);
}

// round 16
// speedup vs baseline: 6.3102x; 1.0158x over previous
#include <cuda_runtime.h>
#include <cuda_fp16.h>
#include <cstdint>

// ============================================================================
// Round 16: R15 + forced 2-CTA/SM co-residency on both MMA kernels
// (__launch_bounds__(256,2) -> <=128 regs) to hide softmax/LDSM phases behind
// the co-resident CTA's MMA issue; split_prep explicit 2-way ILP.
// Arithmetic identical to R15.
// ============================================================================

#define SEQ 2048
#define HID 1024
#define KVD 256
#define SCALE 0.03125f

__device__ __align__(16) __half g_xh[SEQ*HID];
__device__ __align__(16) __half g_wh[1536*HID];
__device__ __align__(16) __half g_Qh[SEQ*HID];
__device__ __align__(16) __half g_Kh[SEQ*KVD];
__device__ __align__(16) __half g_Vth[KVD*SEQ];   // V^T [d][seq]

#define MMA_F16(c, a0,a1,a2,a3, b0,b1) \
    asm volatile("mma.sync.aligned.m16n8k16.row.col.f32.f16.f16.f32 " \
        "{%0,%1,%2,%3}, {%4,%5,%6,%7}, {%8,%9}, {%0,%1,%2,%3};" \
        : "+f"((c)[0]), "+f"((c)[1]), "+f"((c)[2]), "+f"((c)[3]) \
        : "r"(a0), "r"(a1), "r"(a2), "r"(a3), "r"(b0), "r"(b1))

#define LDSM4(r0,r1,r2,r3, a) \
    asm volatile("ldmatrix.sync.aligned.m8n8.x4.shared.b16 {%0,%1,%2,%3}, [%4];" \
        : "=r"(r0), "=r"(r1), "=r"(r2), "=r"(r3) : "r"(a))

#define CP16(dst, src) \
    asm volatile("cp.async.cg.shared.global [%0], [%1], 16;" :: "r"(dst), "l"(src) : "memory")
#define CPC()  asm volatile("cp.async.commit_group;" ::: "memory")
#define CPW1() asm volatile("cp.async.wait_group 1;" ::: "memory")
#define CPW0() asm volatile("cp.async.wait_group 0;" ::: "memory")

__device__ __forceinline__ uint32_t smaddr(const void* p) {
    uint32_t a;
    asm("{ .reg .u64 t; cvta.to.shared.u64 t, %1; cvt.u32.u64 %0, t; }"
        : "=r"(a) : "l"(p));
    return a;
}

// ----------------------------------------------------------------------------
// Prep: x, W -> fp16 planes. Fixed trip counts, explicit 2-way ILP.
// grid 1024 x 256: 262144 threads. x: 524288 float4 -> 2/thread.
// W: 393216 float4 -> 1.5/thread.
// ----------------------------------------------------------------------------
__global__ __launch_bounds__(256)
void split_prep(const float* __restrict__ x, const float* __restrict__ Wq,
                const float* __restrict__ Wk, const float* __restrict__ Wv)
{
    const int idx = blockIdx.x * blockDim.x + threadIdx.x;   // 0..262143

    // ---- x: two independent float4s in flight ----
    {
        float4 v0 = ((const float4*)x)[idx];
        float4 v1 = ((const float4*)x)[idx + 262144];
        __half2 a0 = __floats2half2_rn(v0.x, v0.y);
        __half2 b0 = __floats2half2_rn(v0.z, v0.w);
        __half2 a1 = __floats2half2_rn(v1.x, v1.y);
        __half2 b1 = __floats2half2_rn(v1.z, v1.w);
        ((uint2*)g_xh)[idx]          = make_uint2(*(uint32_t*)&a0, *(uint32_t*)&b0);
        ((uint2*)g_xh)[idx + 262144] = make_uint2(*(uint32_t*)&a1, *(uint32_t*)&b1);
    }

    // ---- W: up to two independent float4s ----
    {
        // first element: i4 = idx
        int i = idx * 4;
        int r = i >> 10;
        float4 v;
        if (r < 1024)      v = *(const float4*)(Wq + i);
        else if (r < 1280) v = *(const float4*)(Wk + i - 1024*1024);
        else               v = *(const float4*)(Wv + i - 1280*1024);
        // second element: i4 = idx + 262144 (rows 1024.. -> K/V region only)
        float4 v2 = make_float4(0.f,0.f,0.f,0.f);
        int has2 = idx < 131072;
        if (has2) {
            int i2 = (idx + 262144) * 4;
            int r2 = i2 >> 10;
            if (r2 < 1280) v2 = *(const float4*)(Wk + i2 - 1024*1024);
            else           v2 = *(const float4*)(Wv + i2 - 1280*1024);
        }
        __half2 a = __floats2half2_rn(v.x, v.y);
        __half2 b = __floats2half2_rn(v.z, v.w);
        ((uint2*)g_wh)[idx] = make_uint2(*(uint32_t*)&a, *(uint32_t*)&b);
        if (has2) {
            __half2 a2 = __floats2half2_rn(v2.x, v2.y);
            __half2 b2 = __floats2half2_rn(v2.z, v2.w);
            ((uint2*)g_wh)[idx + 262144] = make_uint2(*(uint32_t*)&a2, *(uint32_t*)&b2);
        }
    }
}

// ----------------------------------------------------------------------------
// QKV GEMM: [2048 x 1536] = x @ Wcat^T. BM=128, BN=64, BK=32, 8 warps (4x2),
// warp tile 32x32. cp.async double buffered, ldmatrix fragments. 2 CTAs/SM.
// ----------------------------------------------------------------------------
__global__ __launch_bounds__(256, 2)
void qkv_mma()
{
    __shared__ uint32_t sq[2*3840];
    const int tid = threadIdx.x, lane = tid & 31, warp = tid >> 5;
    const int m0 = blockIdx.y * 128, n0 = blockIdx.x * 64;
    const int wm = warp >> 1, wn = warp & 1;
    const uint32_t smb = smaddr(sq);

    float c[2][4][4];
    #pragma unroll
    for (int a = 0; a < 2; a++)
        #pragma unroll
        for (int b = 0; b < 4; b++)
            #pragma unroll
            for (int d = 0; d < 4; d++) c[a][b][d] = 0.f;

    const int ar = tid >> 1, ac = (tid & 1) * 8;
    const int br = tid >> 2, bc = (tid & 3) * 4;
    const __half* xsrc = g_xh + (size_t)(m0 + ar) * HID + ac*2;
    const __half* wsrc = g_wh + (size_t)(n0 + br) * HID + bc*2;
    const uint32_t dA = smb + (ar*20 + ac)*4;
    const uint32_t dB = smb + 10240 + (br*20 + bc)*4;

    const int arow = ((lane>>3)&1)*8 + (lane&7);
    const int ako  = ((lane>>4)&1)*16;
    const int brow = ((lane>>4)&1)*8 + (lane&7);
    const int bko  = ((lane>>3)&1)*16;
    const uint32_t aAddr = smb + (wm*32 + arow)*80 + ako;
    const uint32_t bAddr = smb + 10240 + (wn*32 + brow)*80 + bko;

    {
        CP16(dA, xsrc); CP16(dA + 16, xsrc + 8);
        CP16(dB, wsrc);
        CPC();
    }

    for (int kt = 0; kt < 32; kt++) {
        const int s = kt & 1;
        const uint32_t soff = s * 15360;
        if (kt < 31) {
            const int k1 = (kt+1) * 32;
            const uint32_t so2 = (s^1) * 15360;
            CP16(dA + so2, xsrc + k1); CP16(dA + so2 + 16, xsrc + k1 + 8);
            CP16(dB + so2, wsrc + k1);
            CPC();
            CPW1();
        } else {
            CPW0();
        }
        __syncthreads();

        #pragma unroll
        for (int ks = 0; ks < 2; ks++) {
            uint32_t A0[4], A1[4];
            LDSM4(A0[0],A0[1],A0[2],A0[3], aAddr + soff + ks*32);
            LDSM4(A1[0],A1[1],A1[2],A1[3], aAddr + soff + 1280 + ks*32);
            #pragma unroll
            for (int ntp = 0; ntp < 2; ntp++) {
                uint32_t b0,b1,b2,b3;
                LDSM4(b0,b1,b2,b3, bAddr + soff + ntp*1280 + ks*32);
                MMA_F16(c[0][2*ntp],   A0[0],A0[1],A0[2],A0[3], b0,b1);
                MMA_F16(c[1][2*ntp],   A1[0],A1[1],A1[2],A1[3], b0,b1);
                MMA_F16(c[0][2*ntp+1], A0[0],A0[1],A0[2],A0[3], b2,b3);
                MMA_F16(c[1][2*ntp+1], A1[0],A1[1],A1[2],A1[3], b2,b3);
            }
        }
        __syncthreads();
    }

    #pragma unroll
    for (int mt = 0; mt < 2; mt++) {
        int r0 = m0 + wm*32 + mt*16 + (lane >> 2);
        #pragma unroll
        for (int nt = 0; nt < 4; nt++) {
            int col = n0 + wn*32 + nt*8 + 2*(lane & 3);
            float v0 = c[mt][nt][0], v1 = c[mt][nt][1];
            float v2 = c[mt][nt][2], v3 = c[mt][nt][3];
            if (n0 < 1024) {
                __half2 p0 = __floats2half2_rn(v0*SCALE, v1*SCALE);
                __half2 p1 = __floats2half2_rn(v2*SCALE, v3*SCALE);
                *(__half2*)&g_Qh[(size_t)r0*HID + col]     = p0;
                *(__half2*)&g_Qh[(size_t)(r0+8)*HID + col] = p1;
            } else if (n0 < 1280) {
                int kc2 = col - 1024;
                __half2 p0 = __floats2half2_rn(v0, v1);
                __half2 p1 = __floats2half2_rn(v2, v3);
                *(__half2*)&g_Kh[(size_t)r0*KVD + kc2]     = p0;
                *(__half2*)&g_Kh[(size_t)(r0+8)*KVD + kc2] = p1;
            } else {
                int vc = col - 1280;
                g_Vth[(size_t)vc*SEQ + r0]       = __float2half_rn(v0);
                g_Vth[(size_t)(vc+1)*SEQ + r0]   = __float2half_rn(v1);
                g_Vth[(size_t)vc*SEQ + r0+8]     = __float2half_rn(v2);
                g_Vth[(size_t)(vc+1)*SEQ + r0+8] = __float2half_rn(v3);
            }
        }
    }
}

// ----------------------------------------------------------------------------
// Attention: Br=128 (8 warps x 16 rows, full 64-key width/warp), Bc=64.
// FA2-style register softmax. cp.async double buffered, ldmatrix frags.
// Forced 2 CTAs/SM so a co-resident CTA's MMAs fill this CTA's softmax phase.
// ----------------------------------------------------------------------------
__global__ __launch_bounds__(256, 2)
void attn_mma(float* __restrict__ out)
{
    __shared__ uint32_t sm[2*4608];

    const int tid = threadIdx.x, lane = tid & 31, w = tid >> 5;
    const int h  = blockIdx.y;
    const int qt = gridDim.x - 1 - blockIdx.x;     // longest first
    const int q0 = qt * 128;
    const int kvh = h >> 2;
    const int fq = lane & 3, fr8 = lane >> 2;
    const int warp_row = q0 + w*16 + fr8;
    const uint32_t smb = smaddr(sm);

    // ---- Stage Q (stage-0 region), extract fragments via ldmatrix ----
    {
        const int row = tid >> 1, half = (tid & 1) * 16;
        const __half* qh = g_Qh + (size_t)(q0 + row) * HID + h*64 + half*2;
        #pragma unroll
        for (int g = 0; g < 4; g++)
            *(uint4*)&sm[row*36 + half + g*4] = *(const uint4*)(qh + g*8);
    }
    __syncthreads();

    uint32_t qf[4][4];
    {
        const int qrow = ((lane>>3)&1)*8 + (lane&7);
        const int qko  = ((lane>>4)&1)*16;
        const uint32_t qaddr = smb + (w*16 + qrow)*144 + qko;
        #pragma unroll
        for (int ks = 0; ks < 4; ks++)
            LDSM4(qf[ks][0],qf[ks][1],qf[ks][2],qf[ks][3], qaddr + ks*32);
    }
    __syncthreads();   // Q reads done before prefetch overwrites stage 0

    const int ldr = tid >> 2, seg = tid & 3;
    const uint32_t dK = smb + (ldr*36 + seg*8)*4;
    const uint32_t dV = smb + 9216 + (ldr*36 + seg*8)*4;
    const __half* ksrc = g_Kh  + (size_t)ldr * KVD + kvh*64 + seg*16;
    const __half* vsrc = g_Vth + (size_t)(kvh*64 + ldr) * SEQ + seg*16;

    const int brow = ((lane>>4)&1)*8 + (lane&7);
    const int bko  = ((lane>>3)&1)*16;
    const uint32_t kfrag = smb + brow*144 + bko;
    const uint32_t vfrag = smb + 9216 + brow*144 + bko;

    float o[8][4];
    #pragma unroll
    for (int nt = 0; nt < 8; nt++)
        #pragma unroll
        for (int j = 0; j < 4; j++) o[nt][j] = 0.f;
    float m0 = -1e30f, m1 = -1e30f, l0 = 0.f, l1 = 0.f;

    const int ktmax = 2*qt + 1;

    {
        CP16(dK, ksrc); CP16(dK + 16, ksrc + 8);
        CP16(dV, vsrc); CP16(dV + 16, vsrc + 8);
        CPC();
    }

    for (int kt = 0; kt <= ktmax; kt++) {
        const int s = kt & 1;
        const int k0 = kt * 64;
        const uint32_t soff = s * 18432;

        if (kt < ktmax) {
            const uint32_t so2 = (s^1) * 18432;
            const int k1 = (kt+1) * 64;
            CP16(dK + so2, ksrc + (size_t)k1*KVD); CP16(dK + so2 + 16, ksrc + (size_t)k1*KVD + 8);
            CP16(dV + so2, vsrc + k1);             CP16(dV + so2 + 16, vsrc + k1 + 8);
            CPC();
            CPW1();
        } else {
            CPW0();
        }
        __syncthreads();

        if (k0 <= q0 + w*16 + 15) {
            // ---- Phase 1: S = Qh @ Kh^T ----
            float s4[8][4];
            #pragma unroll
            for (int nt = 0; nt < 8; nt++)
                #pragma unroll
                for (int j = 0; j < 4; j++) s4[nt][j] = 0.f;
            #pragma unroll
            for (int ks = 0; ks < 4; ks++) {
                #pragma unroll
                for (int ntp = 0; ntp < 4; ntp++) {
                    uint32_t b0,b1,b2,b3;
                    LDSM4(b0,b1,b2,b3, kfrag + soff + ntp*2304 + ks*32);
                    MMA_F16(s4[2*ntp],   qf[ks][0],qf[ks][1],qf[ks][2],qf[ks][3], b0,b1);
                    MMA_F16(s4[2*ntp+1], qf[ks][0],qf[ks][1],qf[ks][2],qf[ks][3], b2,b3);
                }
            }

            // Causal mask near the diagonal
            if (k0 + 63 > warp_row) {
                #pragma unroll
                for (int nt = 0; nt < 8; nt++) {
                    int c0 = k0 + nt*8 + 2*fq;
                    if (c0     > warp_row    ) s4[nt][0] = -1e30f;
                    if (c0 + 1 > warp_row    ) s4[nt][1] = -1e30f;
                    if (c0     > warp_row + 8) s4[nt][2] = -1e30f;
                    if (c0 + 1 > warp_row + 8) s4[nt][3] = -1e30f;
                }
            }

            // ---- Warp-local online softmax ----
            float t0 = -1e30f, t1 = -1e30f;
            #pragma unroll
            for (int nt = 0; nt < 8; nt++) {
                t0 = fmaxf(t0, fmaxf(s4[nt][0], s4[nt][1]));
                t1 = fmaxf(t1, fmaxf(s4[nt][2], s4[nt][3]));
            }
            t0 = fmaxf(t0, __shfl_xor_sync(0xffffffffu, t0, 1));
            t0 = fmaxf(t0, __shfl_xor_sync(0xffffffffu, t0, 2));
            t1 = fmaxf(t1, __shfl_xor_sync(0xffffffffu, t1, 1));
            t1 = fmaxf(t1, __shfl_xor_sync(0xffffffffu, t1, 2));
            float mn0 = fmaxf(m0, t0), mn1 = fmaxf(m1, t1);
            float a0 = __expf(m0 - mn0), a1 = __expf(m1 - mn1);
            m0 = mn0; m1 = mn1;

            // exp + pack P into A-fragments
            uint32_t pa[8], pb[8];
            float ls0 = 0.f, ls1 = 0.f;
            #pragma unroll
            for (int nt = 0; nt < 8; nt++) {
                float p0 = __expf(s4[nt][0] - mn0);
                float p1 = __expf(s4[nt][1] - mn0);
                float p2 = __expf(s4[nt][2] - mn1);
                float p3 = __expf(s4[nt][3] - mn1);
                ls0 += p0 + p1; ls1 += p2 + p3;
                __half2 hp0 = __floats2half2_rn(p0, p1);
                __half2 hp1 = __floats2half2_rn(p2, p3);
                pa[nt] = *(uint32_t*)&hp0;
                pb[nt] = *(uint32_t*)&hp1;
            }
            ls0 += __shfl_xor_sync(0xffffffffu, ls0, 1);
            ls0 += __shfl_xor_sync(0xffffffffu, ls0, 2);
            ls1 += __shfl_xor_sync(0xffffffffu, ls1, 1);
            ls1 += __shfl_xor_sync(0xffffffffu, ls1, 2);
            l0 = l0*a0 + ls0; l1 = l1*a1 + ls1;

            // rescale O
            #pragma unroll
            for (int nt = 0; nt < 8; nt++) {
                o[nt][0] *= a0; o[nt][1] *= a0;
                o[nt][2] *= a1; o[nt][3] *= a1;
            }

            // ---- Phase 2: O += Ph @ Vh ----
            #pragma unroll
            for (int ks = 0; ks < 4; ks++) {
                uint32_t A0 = pa[2*ks], A1 = pb[2*ks], A2 = pa[2*ks+1], A3 = pb[2*ks+1];
                #pragma unroll
                for (int ntp = 0; ntp < 4; ntp++) {
                    uint32_t b0,b1,b2,b3;
                    LDSM4(b0,b1,b2,b3, vfrag + soff + ntp*2304 + ks*32);
                    MMA_F16(o[2*ntp],   A0,A1,A2,A3, b0,b1);
                    MMA_F16(o[2*ntp+1], A0,A1,A2,A3, b2,b3);
                }
            }
        }
        __syncthreads();
    }

    // ---- Epilogue ----
    {
        float inv0 = 1.f / l0, inv1 = 1.f / l1;
        #pragma unroll
        for (int nt = 0; nt < 8; nt++) {
            int col = h*64 + nt*8 + 2*fq;
            *(float2*)&out[(size_t)warp_row*HID + col] =
                make_float2(o[nt][0]*inv0, o[nt][1]*inv0);
            *(float2*)&out[(size_t)(warp_row+8)*HID + col] =
                make_float2(o[nt][2]*inv1, o[nt][3]*inv1);
        }
    }
}

// ----------------------------------------------------------------------------
extern "C" void kernel_launch(void* const* d_in, const int* in_sizes, int n_in,
                              void* d_out, int out_size)
{
    const float* x  = (const float*)d_in[0];
    const float* Wq = (const float*)d_in[1];
    const float* Wk = (const float*)d_in[2];
    const float* Wv = (const float*)d_in[3];
    float* out = (float*)d_out;

    split_prep<<<1024, 256>>>(x, Wq, Wk, Wv);
    qkv_mma<<<dim3(24, 16), 256>>>();
    attn_mma<<<dim3(16, 16), 256>>>(out);
}

// round 17
// speedup vs baseline: 8.2681x; 1.3103x over previous
#include <cuda_runtime.h>
#include <cuda_fp16.h>
#include <cstdint>

// ============================================================================
// Round 17: R16 + attention block-schedule rebalance. Classic launch places
// bid and bid+148 on the same SM (LUT[bid%148]); with 256 resident blocks the
// kernel ends when the slowest SM finishes. Map bid->(qt,head) so co-resident
// pairs are complementary (rank j with rank 255-j): all pair sums ~34 units
// vs 56 before. Arithmetic identical to R16.
// ============================================================================

#define SEQ 2048
#define HID 1024
#define KVD 256
#define SCALE 0.03125f

__device__ __align__(16) __half g_xh[SEQ*HID];
__device__ __align__(16) __half g_wh[1536*HID];
__device__ __align__(16) __half g_Qh[SEQ*HID];
__device__ __align__(16) __half g_Kh[SEQ*KVD];
__device__ __align__(16) __half g_Vth[KVD*SEQ];   // V^T [d][seq]

#define MMA_F16(c, a0,a1,a2,a3, b0,b1) \
    asm volatile("mma.sync.aligned.m16n8k16.row.col.f32.f16.f16.f32 " \
        "{%0,%1,%2,%3}, {%4,%5,%6,%7}, {%8,%9}, {%0,%1,%2,%3};" \
        : "+f"((c)[0]), "+f"((c)[1]), "+f"((c)[2]), "+f"((c)[3]) \
        : "r"(a0), "r"(a1), "r"(a2), "r"(a3), "r"(b0), "r"(b1))

#define LDSM4(r0,r1,r2,r3, a) \
    asm volatile("ldmatrix.sync.aligned.m8n8.x4.shared.b16 {%0,%1,%2,%3}, [%4];" \
        : "=r"(r0), "=r"(r1), "=r"(r2), "=r"(r3) : "r"(a))

#define CP16(dst, src) \
    asm volatile("cp.async.cg.shared.global [%0], [%1], 16;" :: "r"(dst), "l"(src) : "memory")
#define CPC()  asm volatile("cp.async.commit_group;" ::: "memory")
#define CPW1() asm volatile("cp.async.wait_group 1;" ::: "memory")
#define CPW0() asm volatile("cp.async.wait_group 0;" ::: "memory")

__device__ __forceinline__ uint32_t smaddr(const void* p) {
    uint32_t a;
    asm("{ .reg .u64 t; cvta.to.shared.u64 t, %1; cvt.u32.u64 %0, t; }"
        : "=r"(a) : "l"(p));
    return a;
}

// ----------------------------------------------------------------------------
// Prep: x, W -> fp16 planes. Fixed trip counts, explicit 2-way ILP.
// ----------------------------------------------------------------------------
__global__ __launch_bounds__(256)
void split_prep(const float* __restrict__ x, const float* __restrict__ Wq,
                const float* __restrict__ Wk, const float* __restrict__ Wv)
{
    const int idx = blockIdx.x * blockDim.x + threadIdx.x;   // 0..262143

    {
        float4 v0 = ((const float4*)x)[idx];
        float4 v1 = ((const float4*)x)[idx + 262144];
        __half2 a0 = __floats2half2_rn(v0.x, v0.y);
        __half2 b0 = __floats2half2_rn(v0.z, v0.w);
        __half2 a1 = __floats2half2_rn(v1.x, v1.y);
        __half2 b1 = __floats2half2_rn(v1.z, v1.w);
        ((uint2*)g_xh)[idx]          = make_uint2(*(uint32_t*)&a0, *(uint32_t*)&b0);
        ((uint2*)g_xh)[idx + 262144] = make_uint2(*(uint32_t*)&a1, *(uint32_t*)&b1);
    }

    {
        int i = idx * 4;
        int r = i >> 10;
        float4 v;
        if (r < 1024)      v = *(const float4*)(Wq + i);
        else if (r < 1280) v = *(const float4*)(Wk + i - 1024*1024);
        else               v = *(const float4*)(Wv + i - 1280*1024);
        float4 v2 = make_float4(0.f,0.f,0.f,0.f);
        int has2 = idx < 131072;
        if (has2) {
            int i2 = (idx + 262144) * 4;
            int r2 = i2 >> 10;
            if (r2 < 1280) v2 = *(const float4*)(Wk + i2 - 1024*1024);
            else           v2 = *(const float4*)(Wv + i2 - 1280*1024);
        }
        __half2 a = __floats2half2_rn(v.x, v.y);
        __half2 b = __floats2half2_rn(v.z, v.w);
        ((uint2*)g_wh)[idx] = make_uint2(*(uint32_t*)&a, *(uint32_t*)&b);
        if (has2) {
            __half2 a2 = __floats2half2_rn(v2.x, v2.y);
            __half2 b2 = __floats2half2_rn(v2.z, v2.w);
            ((uint2*)g_wh)[idx + 262144] = make_uint2(*(uint32_t*)&a2, *(uint32_t*)&b2);
        }
    }
}

// ----------------------------------------------------------------------------
// QKV GEMM: [2048 x 1536] = x @ Wcat^T. BM=128, BN=64, BK=32, 8 warps (4x2),
// warp tile 32x32. cp.async double buffered, ldmatrix fragments. 2 CTAs/SM.
// ----------------------------------------------------------------------------
__global__ __launch_bounds__(256, 2)
void qkv_mma()
{
    __shared__ uint32_t sq[2*3840];
    const int tid = threadIdx.x, lane = tid & 31, warp = tid >> 5;
    const int m0 = blockIdx.y * 128, n0 = blockIdx.x * 64;
    const int wm = warp >> 1, wn = warp & 1;
    const uint32_t smb = smaddr(sq);

    float c[2][4][4];
    #pragma unroll
    for (int a = 0; a < 2; a++)
        #pragma unroll
        for (int b = 0; b < 4; b++)
            #pragma unroll
            for (int d = 0; d < 4; d++) c[a][b][d] = 0.f;

    const int ar = tid >> 1, ac = (tid & 1) * 8;
    const int br = tid >> 2, bc = (tid & 3) * 4;
    const __half* xsrc = g_xh + (size_t)(m0 + ar) * HID + ac*2;
    const __half* wsrc = g_wh + (size_t)(n0 + br) * HID + bc*2;
    const uint32_t dA = smb + (ar*20 + ac)*4;
    const uint32_t dB = smb + 10240 + (br*20 + bc)*4;

    const int arow = ((lane>>3)&1)*8 + (lane&7);
    const int ako  = ((lane>>4)&1)*16;
    const int brow = ((lane>>4)&1)*8 + (lane&7);
    const int bko  = ((lane>>3)&1)*16;
    const uint32_t aAddr = smb + (wm*32 + arow)*80 + ako;
    const uint32_t bAddr = smb + 10240 + (wn*32 + brow)*80 + bko;

    {
        CP16(dA, xsrc); CP16(dA + 16, xsrc + 8);
        CP16(dB, wsrc);
        CPC();
    }

    for (int kt = 0; kt < 32; kt++) {
        const int s = kt & 1;
        const uint32_t soff = s * 15360;
        if (kt < 31) {
            const int k1 = (kt+1) * 32;
            const uint32_t so2 = (s^1) * 15360;
            CP16(dA + so2, xsrc + k1); CP16(dA + so2 + 16, xsrc + k1 + 8);
            CP16(dB + so2, wsrc + k1);
            CPC();
            CPW1();
        } else {
            CPW0();
        }
        __syncthreads();

        #pragma unroll
        for (int ks = 0; ks < 2; ks++) {
            uint32_t A0[4], A1[4];
            LDSM4(A0[0],A0[1],A0[2],A0[3], aAddr + soff + ks*32);
            LDSM4(A1[0],A1[1],A1[2],A1[3], aAddr + soff + 1280 + ks*32);
            #pragma unroll
            for (int ntp = 0; ntp < 2; ntp++) {
                uint32_t b0,b1,b2,b3;
                LDSM4(b0,b1,b2,b3, bAddr + soff + ntp*1280 + ks*32);
                MMA_F16(c[0][2*ntp],   A0[0],A0[1],A0[2],A0[3], b0,b1);
                MMA_F16(c[1][2*ntp],   A1[0],A1[1],A1[2],A1[3], b0,b1);
                MMA_F16(c[0][2*ntp+1], A0[0],A0[1],A0[2],A0[3], b2,b3);
                MMA_F16(c[1][2*ntp+1], A1[0],A1[1],A1[2],A1[3], b2,b3);
            }
        }
        __syncthreads();
    }

    #pragma unroll
    for (int mt = 0; mt < 2; mt++) {
        int r0 = m0 + wm*32 + mt*16 + (lane >> 2);
        #pragma unroll
        for (int nt = 0; nt < 4; nt++) {
            int col = n0 + wn*32 + nt*8 + 2*(lane & 3);
            float v0 = c[mt][nt][0], v1 = c[mt][nt][1];
            float v2 = c[mt][nt][2], v3 = c[mt][nt][3];
            if (n0 < 1024) {
                __half2 p0 = __floats2half2_rn(v0*SCALE, v1*SCALE);
                __half2 p1 = __floats2half2_rn(v2*SCALE, v3*SCALE);
                *(__half2*)&g_Qh[(size_t)r0*HID + col]     = p0;
                *(__half2*)&g_Qh[(size_t)(r0+8)*HID + col] = p1;
            } else if (n0 < 1280) {
                int kc2 = col - 1024;
                __half2 p0 = __floats2half2_rn(v0, v1);
                __half2 p1 = __floats2half2_rn(v2, v3);
                *(__half2*)&g_Kh[(size_t)r0*KVD + kc2]     = p0;
                *(__half2*)&g_Kh[(size_t)(r0+8)*KVD + kc2] = p1;
            } else {
                int vc = col - 1280;
                g_Vth[(size_t)vc*SEQ + r0]       = __float2half_rn(v0);
                g_Vth[(size_t)(vc+1)*SEQ + r0]   = __float2half_rn(v1);
                g_Vth[(size_t)vc*SEQ + r0+8]     = __float2half_rn(v2);
                g_Vth[(size_t)(vc+1)*SEQ + r0+8] = __float2half_rn(v3);
            }
        }
    }
}

// ----------------------------------------------------------------------------
// Attention: Br=128 (8 warps x 16 rows, full 64-key width/warp), Bc=64.
// 1D grid 256; balanced bid->(qt,head) schedule: rank = bid<148 ? bid
// : 403-bid, qt = 15-(rank>>4), h = rank&15. Co-resident SM pairs
// (bid j, bid j+148) then hold complementary workloads (sum ~34 units).
// ----------------------------------------------------------------------------
__global__ __launch_bounds__(256, 2)
void attn_mma(float* __restrict__ out)
{
    __shared__ uint32_t sm[2*4608];

    const int tid = threadIdx.x, lane = tid & 31, w = tid >> 5;
    const int bid = blockIdx.x;
    const int rank = (bid < 148) ? bid : (403 - bid);
    const int qt = 15 - (rank >> 4);
    const int h  = rank & 15;
    const int q0 = qt * 128;
    const int kvh = h >> 2;
    const int fq = lane & 3, fr8 = lane >> 2;
    const int warp_row = q0 + w*16 + fr8;
    const uint32_t smb = smaddr(sm);

    // ---- Stage Q (stage-0 region), extract fragments via ldmatrix ----
    {
        const int row = tid >> 1, half = (tid & 1) * 16;
        const __half* qh = g_Qh + (size_t)(q0 + row) * HID + h*64 + half*2;
        #pragma unroll
        for (int g = 0; g < 4; g++)
            *(uint4*)&sm[row*36 + half + g*4] = *(const uint4*)(qh + g*8);
    }
    __syncthreads();

    uint32_t qf[4][4];
    {
        const int qrow = ((lane>>3)&1)*8 + (lane&7);
        const int qko  = ((lane>>4)&1)*16;
        const uint32_t qaddr = smb + (w*16 + qrow)*144 + qko;
        #pragma unroll
        for (int ks = 0; ks < 4; ks++)
            LDSM4(qf[ks][0],qf[ks][1],qf[ks][2],qf[ks][3], qaddr + ks*32);
    }
    __syncthreads();   // Q reads done before prefetch overwrites stage 0

    const int ldr = tid >> 2, seg = tid & 3;
    const uint32_t dK = smb + (ldr*36 + seg*8)*4;
    const uint32_t dV = smb + 9216 + (ldr*36 + seg*8)*4;
    const __half* ksrc = g_Kh  + (size_t)ldr * KVD + kvh*64 + seg*16;
    const __half* vsrc = g_Vth + (size_t)(kvh*64 + ldr) * SEQ + seg*16;

    const int brow = ((lane>>4)&1)*8 + (lane&7);
    const int bko  = ((lane>>3)&1)*16;
    const uint32_t kfrag = smb + brow*144 + bko;
    const uint32_t vfrag = smb + 9216 + brow*144 + bko;

    float o[8][4];
    #pragma unroll
    for (int nt = 0; nt < 8; nt++)
        #pragma unroll
        for (int j = 0; j < 4; j++) o[nt][j] = 0.f;
    float m0 = -1e30f, m1 = -1e30f, l0 = 0.f, l1 = 0.f;

    const int ktmax = 2*qt + 1;

    {
        CP16(dK, ksrc); CP16(dK + 16, ksrc + 8);
        CP16(dV, vsrc); CP16(dV + 16, vsrc + 8);
        CPC();
    }

    for (int kt = 0; kt <= ktmax; kt++) {
        const int s = kt & 1;
        const int k0 = kt * 64;
        const uint32_t soff = s * 18432;

        if (kt < ktmax) {
            const uint32_t so2 = (s^1) * 18432;
            const int k1 = (kt+1) * 64;
            CP16(dK + so2, ksrc + (size_t)k1*KVD); CP16(dK + so2 + 16, ksrc + (size_t)k1*KVD + 8);
            CP16(dV + so2, vsrc + k1);             CP16(dV + so2 + 16, vsrc + k1 + 8);
            CPC();
            CPW1();
        } else {
            CPW0();
        }
        __syncthreads();

        if (k0 <= q0 + w*16 + 15) {
            // ---- Phase 1: S = Qh @ Kh^T ----
            float s4[8][4];
            #pragma unroll
            for (int nt = 0; nt < 8; nt++)
                #pragma unroll
                for (int j = 0; j < 4; j++) s4[nt][j] = 0.f;
            #pragma unroll
            for (int ks = 0; ks < 4; ks++) {
                #pragma unroll
                for (int ntp = 0; ntp < 4; ntp++) {
                    uint32_t b0,b1,b2,b3;
                    LDSM4(b0,b1,b2,b3, kfrag + soff + ntp*2304 + ks*32);
                    MMA_F16(s4[2*ntp],   qf[ks][0],qf[ks][1],qf[ks][2],qf[ks][3], b0,b1);
                    MMA_F16(s4[2*ntp+1], qf[ks][0],qf[ks][1],qf[ks][2],qf[ks][3], b2,b3);
                }
            }

            // Causal mask near the diagonal
            if (k0 + 63 > warp_row) {
                #pragma unroll
                for (int nt = 0; nt < 8; nt++) {
                    int c0 = k0 + nt*8 + 2*fq;
                    if (c0     > warp_row    ) s4[nt][0] = -1e30f;
                    if (c0 + 1 > warp_row    ) s4[nt][1] = -1e30f;
                    if (c0     > warp_row + 8) s4[nt][2] = -1e30f;
                    if (c0 + 1 > warp_row + 8) s4[nt][3] = -1e30f;
                }
            }

            // ---- Warp-local online softmax ----
            float t0 = -1e30f, t1 = -1e30f;
            #pragma unroll
            for (int nt = 0; nt < 8; nt++) {
                t0 = fmaxf(t0, fmaxf(s4[nt][0], s4[nt][1]));
                t1 = fmaxf(t1, fmaxf(s4[nt][2], s4[nt][3]));
            }
            t0 = fmaxf(t0, __shfl_xor_sync(0xffffffffu, t0, 1));
            t0 = fmaxf(t0, __shfl_xor_sync(0xffffffffu, t0, 2));
            t1 = fmaxf(t1, __shfl_xor_sync(0xffffffffu, t1, 1));
            t1 = fmaxf(t1, __shfl_xor_sync(0xffffffffu, t1, 2));
            float mn0 = fmaxf(m0, t0), mn1 = fmaxf(m1, t1);
            float a0 = __expf(m0 - mn0), a1 = __expf(m1 - mn1);
            m0 = mn0; m1 = mn1;

            // exp + pack P into A-fragments
            uint32_t pa[8], pb[8];
            float ls0 = 0.f, ls1 = 0.f;
            #pragma unroll
            for (int nt = 0; nt < 8; nt++) {
                float p0 = __expf(s4[nt][0] - mn0);
                float p1 = __expf(s4[nt][1] - mn0);
                float p2 = __expf(s4[nt][2] - mn1);
                float p3 = __expf(s4[nt][3] - mn1);
                ls0 += p0 + p1; ls1 += p2 + p3;
                __half2 hp0 = __floats2half2_rn(p0, p1);
                __half2 hp1 = __floats2half2_rn(p2, p3);
                pa[nt] = *(uint32_t*)&hp0;
                pb[nt] = *(uint32_t*)&hp1;
            }
            ls0 += __shfl_xor_sync(0xffffffffu, ls0, 1);
            ls0 += __shfl_xor_sync(0xffffffffu, ls0, 2);
            ls1 += __shfl_xor_sync(0xffffffffu, ls1, 1);
            ls1 += __shfl_xor_sync(0xffffffffu, ls1, 2);
            l0 = l0*a0 + ls0; l1 = l1*a1 + ls1;

            // rescale O
            #pragma unroll
            for (int nt = 0; nt < 8; nt++) {
                o[nt][0] *= a0; o[nt][1] *= a0;
                o[nt][2] *= a1; o[nt][3] *= a1;
            }

            // ---- Phase 2: O += Ph @ Vh ----
            #pragma unroll
            for (int ks = 0; ks < 4; ks++) {
                uint32_t A0 = pa[2*ks], A1 = pb[2*ks], A2 = pa[2*ks+1], A3 = pb[2*ks+1];
                #pragma unroll
                for (int ntp = 0; ntp < 4; ntp++) {
                    uint32_t b0,b1,b2,b3;
                    LDSM4(b0,b1,b2,b3, vfrag + soff + ntp*2304 + ks*32);
                    MMA_F16(o[2*ntp],   A0,A1,A2,A3, b0,b1);
                    MMA_F16(o[2*ntp+1], A0,A1,A2,A3, b2,b3);
                }
            }
        }
        __syncthreads();
    }

    // ---- Epilogue ----
    {
        float inv0 = 1.f / l0, inv1 = 1.f / l1;
        #pragma unroll
        for (int nt = 0; nt < 8; nt++) {
            int col = h*64 + nt*8 + 2*fq;
            *(float2*)&out[(size_t)warp_row*HID + col] =
                make_float2(o[nt][0]*inv0, o[nt][1]*inv0);
            *(float2*)&out[(size_t)(warp_row+8)*HID + col] =
                make_float2(o[nt][2]*inv1, o[nt][3]*inv1);
        }
    }
}

// ----------------------------------------------------------------------------
extern "C" void kernel_launch(void* const* d_in, const int* in_sizes, int n_in,
                              void* d_out, int out_size)
{
    const float* x  = (const float*)d_in[0];
    const float* Wq = (const float*)d_in[1];
    const float* Wk = (const float*)d_in[2];
    const float* Wv = (const float*)d_in[3];
    float* out = (float*)d_out;

    split_prep<<<1024, 256>>>(x, Wq, Wk, Wv);
    qkv_mma<<<dim3(24, 16), 256>>>();
    attn_mma<<<256, 256>>>(out);
}